// round 7
// baseline (speedup 1.0000x reference)
#include <cuda_runtime.h>
#include <math.h>
#include <stdint.h>

#define E 4
#define DIN 256
#define D 256
#define NB 16
#define T 1024
#define M (NB*T)            // 16384 rows per expert
#define EMD ((size_t)E*M*D) // 64MB fp32

#define CCH 16              // scan chunks
#define CLEN (T/CCH)        // 64
#define LANES (E*NB*D)      // 8192

// Scratch (static device globals)
__device__ float g_ir[EMD];
__device__ float g_ii[EMD];
__device__ float g_o [EMD];
__device__ float g_out[EMD];
__device__ float g_fr[E*D], g_fi[E*D], g_gam[E*D];
__device__ float g_finr[LANES*CCH], g_fini[LANES*CCH];
__device__ float g_Sr[LANES*CCH],  g_Si[LANES*CCH];
__device__ float g_Pr[E*CLEN*D],   g_Pi[E*CLEN*D];   // f^(j+1) tables

// ---------------- tf32 tensor-core GEMM core -------------------------------------
// Block 128x64x16, double-buffered smem + register-staged prefetch.
// 256 threads = 8 warps (4m x 2n), warp tile 32x32.
#define BM 128
#define BN 64
#define BKK 16
#define ASS 20   // 16 + 4 pad
#define BSS 72   // 64 + 8 pad

__device__ __forceinline__ uint32_t f2tf(float f) {
    uint32_t u; asm("cvt.rna.tf32.f32 %0, %1;" : "=r"(u) : "f"(f)); return u;
}

// CORR: 0 = none, 1 = add Re(S*P), 2 = add Im(S*P)
template<int CORR>
__device__ __forceinline__ float4 corr_apply(float4 v, int gr, int e, int dcol) {
    if (CORR == 0) return v;
    int t = gr & (T-1); int b = gr >> 10;
    int ch = t >> 6, toff = t & (CLEN-1);
    if (ch > 0) {
        int sidx = ((e*NB + b)*CCH + ch - 1)*D + dcol;
        int pidx = (e*CLEN + toff)*D + dcol;
        float4 sr = *(const float4*)(g_Sr + sidx);
        float4 si = *(const float4*)(g_Si + sidx);
        float4 pr = *(const float4*)(g_Pr + pidx);
        float4 pi = *(const float4*)(g_Pi + pidx);
        if (CORR == 1) {
            v.x += sr.x*pr.x - si.x*pi.x; v.y += sr.y*pr.y - si.y*pi.y;
            v.z += sr.z*pr.z - si.z*pi.z; v.w += sr.w*pr.w - si.w*pi.w;
        } else {
            v.x += sr.x*pi.x + si.x*pr.x; v.y += sr.y*pi.y + si.y*pr.y;
            v.z += sr.z*pi.z + si.z*pr.z; v.w += sr.w*pi.w + si.w*pr.w;
        }
    }
    return v;
}

template<int SGN, int CORR>
__device__ __forceinline__ void gemm_mma(
    const float* __restrict__ A,   // M x 256 row-major (expert base)
    const float* __restrict__ W,   // 256 x 256 row-major
    int m0, int n0, int e, float (&acc)[2][4][4],
    uint32_t (*As)[BM*ASS], uint32_t (*Bs)[BKK*BSS], int tid)
{
    const int lane = tid & 31, wid = tid >> 5;
    const int g = lane >> 2, tg = lane & 3;
    const int wm0 = (wid & 3) * 32, wn0 = (wid >> 2) * 32;
    const int ar = tid >> 2, ac = (tid & 3) * 4;      // A rows ar, ar+64
    const int br = tid >> 4, bc = (tid & 15) * 4;

    float4 ra0, ra1, rb;
    ra0 = corr_apply<CORR>(*(const float4*)(A + (size_t)(m0+ar   )*256 + ac), m0+ar,    e, ac);
    ra1 = corr_apply<CORR>(*(const float4*)(A + (size_t)(m0+ar+64)*256 + ac), m0+ar+64, e, ac);
    rb  = *(const float4*)(W + (size_t)br*256 + n0 + bc);
    __syncthreads();   // protect smem vs prior use
    int cur = 0;
    #pragma unroll 4
    for (int it = 0; it < 256/BKK; it++) {
        // store staged regs -> smem[cur]
        *(uint4*)&As[cur][ ar     *ASS + ac] =
            make_uint4(f2tf(ra0.x), f2tf(ra0.y), f2tf(ra0.z), f2tf(ra0.w));
        *(uint4*)&As[cur][(ar+64) *ASS + ac] =
            make_uint4(f2tf(ra1.x), f2tf(ra1.y), f2tf(ra1.z), f2tf(ra1.w));
        if (SGN < 0) { rb.x=-rb.x; rb.y=-rb.y; rb.z=-rb.z; rb.w=-rb.w; }
        *(uint4*)&Bs[cur][br*BSS + bc] =
            make_uint4(f2tf(rb.x), f2tf(rb.y), f2tf(rb.z), f2tf(rb.w));
        __syncthreads();
        if (it < 256/BKK - 1) {
            int k0 = (it+1)*BKK;
            ra0 = corr_apply<CORR>(*(const float4*)(A + (size_t)(m0+ar   )*256 + k0 + ac), m0+ar,    e, k0+ac);
            ra1 = corr_apply<CORR>(*(const float4*)(A + (size_t)(m0+ar+64)*256 + k0 + ac), m0+ar+64, e, k0+ac);
            rb  = *(const float4*)(W + (size_t)(k0+br)*256 + n0 + bc);
        }
        #pragma unroll
        for (int kk = 0; kk < BKK; kk += 8) {
            uint32_t a[2][4], b[4][2];
            #pragma unroll
            for (int mi = 0; mi < 2; mi++) {
                const uint32_t* base = As[cur] + (wm0 + mi*16 + g)*ASS + kk + tg;
                a[mi][0] = base[0];
                a[mi][1] = base[8*ASS];
                a[mi][2] = base[4];
                a[mi][3] = base[8*ASS + 4];
            }
            #pragma unroll
            for (int ni = 0; ni < 4; ni++) {
                const uint32_t* base = Bs[cur] + (kk + tg)*BSS + wn0 + ni*8 + g;
                b[ni][0] = base[0];
                b[ni][1] = base[4*BSS];
            }
            #pragma unroll
            for (int mi = 0; mi < 2; mi++)
                #pragma unroll
                for (int ni = 0; ni < 4; ni++)
                    asm volatile(
                        "mma.sync.aligned.m16n8k8.row.col.f32.tf32.tf32.f32 "
                        "{%0,%1,%2,%3}, {%4,%5,%6,%7}, {%8,%9}, {%0,%1,%2,%3};"
                        : "+f"(acc[mi][ni][0]), "+f"(acc[mi][ni][1]),
                          "+f"(acc[mi][ni][2]), "+f"(acc[mi][ni][3])
                        : "r"(a[mi][0]), "r"(a[mi][1]), "r"(a[mi][2]), "r"(a[mi][3]),
                          "r"(b[ni][0]), "r"(b[ni][1]));
        }
        cur ^= 1;
    }
}

// ---------------- params ---------------------------------------------------------
__global__ void k_params(const float* __restrict__ pl) {
    int i = blockIdx.x*blockDim.x + threadIdx.x;
    if (i < E*D) {
        float nu  = expf(pl[i]);
        float th  = expf(pl[E*D + i]);
        float gm  = expf(pl[2*E*D + i]);
        float mag = expf(-nu);
        g_fr[i]  = mag * cosf(th);
        g_fi[i]  = mag * sinf(th);
        g_gam[i] = gm;
    }
}

// ---------------- power table: g_P[e][j][d] = f^(j+1) ----------------------------
__global__ void k_powers() {
    int i = blockIdx.x*blockDim.x + threadIdx.x;   // e*D + d
    if (i < E*D) {
        float fr = g_fr[i], fi = g_fi[i];
        int e = i / D, d = i % D;
        float wr = fr, wi = fi;
        for (int j = 0; j < CLEN; j++) {
            g_Pr[(e*CLEN + j)*D + d] = wr;
            g_Pi[(e*CLEN + j)*D + d] = wi;
            float nr = wr*fr - wi*fi, ni2 = wr*fi + wi*fr;
            wr = nr; wi = ni2;
        }
    }
}

// ---------------- in_proj --------------------------------------------------------
__global__ void __launch_bounds__(256) k_inproj(
    const float* __restrict__ x, const float* __restrict__ w,
    const float* __restrict__ bias)
{
    __shared__ uint32_t As[2][BM*ASS];
    __shared__ uint32_t Bs[2][BKK*BSS];
    int m0 = blockIdx.x*BM, n0 = blockIdx.y*BN;
    int ke = blockIdx.z; int k = ke / E; int e = ke % E;
    float acc[2][4][4] = {};
    gemm_mma<1,0>(x, w + (size_t)ke*DIN*D, m0, n0, e, acc, As, Bs, threadIdx.x);
    int lane = threadIdx.x & 31, wid = threadIdx.x >> 5;
    int g = lane >> 2, tg = lane & 3;
    int wm0 = (wid & 3) * 32, wn0 = (wid >> 2) * 32;
    float* dst = (k == 0) ? g_ir : (k == 1) ? g_ii : g_o;
    #pragma unroll
    for (int mi = 0; mi < 2; mi++) {
        int r0 = m0 + wm0 + mi*16 + g;
        #pragma unroll
        for (int ni = 0; ni < 4; ni++) {
            int c = n0 + wn0 + ni*8 + 2*tg;
            float b0 = bias[ke*D + c], b1 = bias[ke*D + c + 1];
            float s0 = (k < 2) ? g_gam[e*D + c]     : 1.0f;
            float s1 = (k < 2) ? g_gam[e*D + c + 1] : 1.0f;
            float2 v0 = make_float2((acc[mi][ni][0] + b0) * s0, (acc[mi][ni][1] + b1) * s1);
            float2 v1 = make_float2((acc[mi][ni][2] + b0) * s0, (acc[mi][ni][3] + b1) * s1);
            *(float2*)&dst[((size_t)e*M + r0    )*D + c] = v0;
            *(float2*)&dst[((size_t)e*M + r0 + 8)*D + c] = v1;
        }
    }
}

// ---------------- chunked LRU scan: local pass (in place) ------------------------
__global__ void k_scan1() {
    int i = blockIdx.x*blockDim.x + threadIdx.x;   // (eb, c, d)
    int d = i % D; int c = (i / D) % CCH; int eb = i / (D*CCH);
    int e = eb / NB;
    float fr = g_fr[e*D+d], fi = g_fi[e*D+d];
    float hr = 0.f, hi = 0.f;
    size_t idx = ((size_t)eb*T + (size_t)c*CLEN)*D + d;
    #pragma unroll 8
    for (int t = 0; t < CLEN; t++, idx += D) {
        float ur = g_ir[idx], ui = g_ii[idx];
        float nr = fmaf(fr, hr, fmaf(-fi, hi, ur));
        float ni2 = fmaf(fr, hi, fmaf( fi, hr, ui));
        hr = nr; hi = ni2;
        g_ir[idx] = hr; g_ii[idx] = hi;
    }
    g_finr[i] = hr; g_fini[i] = hi;
}

// ---------------- carry combine: S_c; emit hidden --------------------------------
__global__ void k_carry(float* __restrict__ hid) {
    int i = blockIdx.x*blockDim.x + threadIdx.x;   // (eb, d)
    int d = i % D; int eb = i / D; int e = eb / NB, b = eb % NB;
    float fr = g_fr[e*D+d], fi = g_fi[e*D+d];
    float pr = fr, pi = fi;                         // f^CLEN via 6 squarings
    #pragma unroll
    for (int s = 0; s < 6; s++) { float nr = pr*pr - pi*pi, ni2 = 2.f*pr*pi; pr = nr; pi = ni2; }
    float sr = 0.f, si = 0.f;
    #pragma unroll
    for (int c = 0; c < CCH; c++) {
        int j = (eb*CCH + c)*D + d;
        float tr = pr*sr - pi*si + g_finr[j];
        float ti = pr*si + pi*sr + g_fini[j];
        sr = tr; si = ti;
        g_Sr[j] = sr; g_Si[j] = si;
    }
    hid[b*(2*E*D) + e*D + d]         = sr;
    hid[b*(2*E*D) + E*D + e*D + d]   = si;
}

// ---------------- mid (correction fused into A loads) ----------------------------
__global__ void __launch_bounds__(256) k_mid(
    const float* __restrict__ mw, const float* __restrict__ mb)
{
    __shared__ uint32_t As[2][BM*ASS];
    __shared__ uint32_t Bs[2][BKK*BSS];
    int m0 = blockIdx.x*BM, n0 = blockIdx.y*BN, e = blockIdx.z;
    float acc[2][4][4] = {};
    gemm_mma< 1,1>(g_ir + (size_t)e*M*D, mw + (size_t)e*D*D,     m0, n0, e, acc, As, Bs, threadIdx.x);
    gemm_mma<-1,2>(g_ii + (size_t)e*M*D, mw + (size_t)(E+e)*D*D, m0, n0, e, acc, As, Bs, threadIdx.x);
    int lane = threadIdx.x & 31, wid = threadIdx.x >> 5;
    int g = lane >> 2, tg = lane & 3;
    int wm0 = (wid & 3) * 32, wn0 = (wid >> 2) * 32;
    #pragma unroll
    for (int mi = 0; mi < 2; mi++) {
        int r0 = m0 + wm0 + mi*16 + g;
        #pragma unroll
        for (int ni = 0; ni < 4; ni++) {
            int c = n0 + wn0 + ni*8 + 2*tg;
            float b0 = mb[e*D+c]   - mb[(E+e)*D+c];
            float b1 = mb[e*D+c+1] - mb[(E+e)*D+c+1];
            size_t i0 = ((size_t)e*M + r0    )*D + c;
            size_t i1 = ((size_t)e*M + r0 + 8)*D + c;
            float2 o0 = *(const float2*)&g_o[i0];
            float2 o1 = *(const float2*)&g_o[i1];
            *(float2*)&g_out[i0] = make_float2(acc[mi][ni][0] + b0 + o0.x, acc[mi][ni][1] + b1 + o0.y);
            *(float2*)&g_out[i1] = make_float2(acc[mi][ni][2] + b0 + o1.x, acc[mi][ni][3] + b1 + o1.y);
        }
    }
}

// ---------------- ff1: h1 = gelu(out@W1 + b1)  (h1 -> g_ir) ----------------------
__device__ __forceinline__ float gelu_f(float v) {
    return 0.5f * v * (1.0f + erff(v * 0.70710678118654752f));
}

__global__ void __launch_bounds__(256) k_ff1(
    const float* __restrict__ w1, const float* __restrict__ b1)
{
    __shared__ uint32_t As[2][BM*ASS];
    __shared__ uint32_t Bs[2][BKK*BSS];
    int m0 = blockIdx.x*BM, n0 = blockIdx.y*BN, e = blockIdx.z;
    float acc[2][4][4] = {};
    gemm_mma<1,0>(g_out + (size_t)e*M*D, w1 + (size_t)e*D*D, m0, n0, e, acc, As, Bs, threadIdx.x);
    int lane = threadIdx.x & 31, wid = threadIdx.x >> 5;
    int g = lane >> 2, tg = lane & 3;
    int wm0 = (wid & 3) * 32, wn0 = (wid >> 2) * 32;
    #pragma unroll
    for (int mi = 0; mi < 2; mi++) {
        int r0 = m0 + wm0 + mi*16 + g;
        #pragma unroll
        for (int ni = 0; ni < 4; ni++) {
            int c = n0 + wn0 + ni*8 + 2*tg;
            float b0 = b1[e*D+c], bb1 = b1[e*D+c+1];
            *(float2*)&g_ir[((size_t)e*M + r0    )*D + c] =
                make_float2(gelu_f(acc[mi][ni][0] + b0), gelu_f(acc[mi][ni][1] + bb1));
            *(float2*)&g_ir[((size_t)e*M + r0 + 8)*D + c] =
                make_float2(gelu_f(acc[mi][ni][2] + b0), gelu_f(acc[mi][ni][3] + bb1));
        }
    }
}

// ---------------- ff2: h2 = h1@W2 + b2 + out   (h2 -> g_ii) ----------------------
__global__ void __launch_bounds__(256) k_ff2(
    const float* __restrict__ w2, const float* __restrict__ b2)
{
    __shared__ uint32_t As[2][BM*ASS];
    __shared__ uint32_t Bs[2][BKK*BSS];
    int m0 = blockIdx.x*BM, n0 = blockIdx.y*BN, e = blockIdx.z;
    float acc[2][4][4] = {};
    gemm_mma<1,0>(g_ir + (size_t)e*M*D, w2 + (size_t)e*D*D, m0, n0, e, acc, As, Bs, threadIdx.x);
    int lane = threadIdx.x & 31, wid = threadIdx.x >> 5;
    int g = lane >> 2, tg = lane & 3;
    int wm0 = (wid & 3) * 32, wn0 = (wid >> 2) * 32;
    #pragma unroll
    for (int mi = 0; mi < 2; mi++) {
        int r0 = m0 + wm0 + mi*16 + g;
        #pragma unroll
        for (int ni = 0; ni < 4; ni++) {
            int c = n0 + wn0 + ni*8 + 2*tg;
            float b0 = b2[e*D+c], b1v = b2[e*D+c+1];
            size_t i0 = ((size_t)e*M + r0    )*D + c;
            size_t i1 = ((size_t)e*M + r0 + 8)*D + c;
            float2 o0 = *(const float2*)&g_out[i0];
            float2 o1 = *(const float2*)&g_out[i1];
            *(float2*)&g_ii[i0] = make_float2(acc[mi][ni][0] + b0 + o0.x, acc[mi][ni][1] + b1v + o0.y);
            *(float2*)&g_ii[i1] = make_float2(acc[mi][ni][2] + b0 + o1.x, acc[mi][ni][3] + b1v + o1.y);
        }
    }
}

// ---------------- LayerNorm over (E,D) per (b,t) ---------------------------------
__global__ void k_ln(const float* __restrict__ lnw, const float* __restrict__ lnb,
                     float* __restrict__ out)
{
    int bt = blockIdx.x;          // 0..M-1
    int d  = threadIdx.x;         // 0..255
    float v[E]; float s = 0.f, s2 = 0.f;
    #pragma unroll
    for (int e = 0; e < E; e++) {
        float x = g_ii[((size_t)e*M + bt)*D + d];
        v[e] = x; s += x; s2 += x*x;
    }
    __shared__ float red[2][8];
    #pragma unroll
    for (int o = 16; o > 0; o >>= 1) {
        s  += __shfl_down_sync(0xffffffffu, s,  o);
        s2 += __shfl_down_sync(0xffffffffu, s2, o);
    }
    int lane = d & 31, w = d >> 5;
    if (lane == 0) { red[0][w] = s; red[1][w] = s2; }
    __syncthreads();
    if (w == 0) {
        s  = (lane < 8) ? red[0][lane] : 0.f;
        s2 = (lane < 8) ? red[1][lane] : 0.f;
        #pragma unroll
        for (int o = 4; o > 0; o >>= 1) {
            s  += __shfl_down_sync(0xffffffffu, s,  o);
            s2 += __shfl_down_sync(0xffffffffu, s2, o);
        }
        if (lane == 0) { red[0][0] = s; red[1][0] = s2; }
    }
    __syncthreads();
    float mean = red[0][0] * (1.0f/1024.0f);
    float var  = red[1][0] * (1.0f/1024.0f) - mean*mean;
    float rinv = rsqrtf(var + 1e-5f);
    #pragma unroll
    for (int e = 0; e < E; e++) {
        out[((size_t)e*M + bt)*D + d] =
            (v[e] - mean) * rinv * lnw[e*D + d] + lnb[e*D + d];
    }
}

// ---------------- launch ---------------------------------------------------------
extern "C" void kernel_launch(void* const* d_in, const int* in_sizes, int n_in,
                              void* d_out, int out_size)
{
    (void)in_sizes; (void)n_in; (void)out_size;
    const float* x   = (const float*)d_in[0];
    const float* ipw = (const float*)d_in[1];
    const float* ipb = (const float*)d_in[2];
    const float* pl  = (const float*)d_in[3];
    const float* mw  = (const float*)d_in[4];
    const float* mb  = (const float*)d_in[5];
    const float* fw1 = (const float*)d_in[6];
    const float* fb1 = (const float*)d_in[7];
    const float* fw2 = (const float*)d_in[8];
    const float* fb2 = (const float*)d_in[9];
    const float* lnw = (const float*)d_in[10];
    const float* lnb = (const float*)d_in[11];
    float* out = (float*)d_out;

    k_params<<<4, 256>>>(pl);
    k_powers<<<4, 256>>>();
    dim3 gin(M/BM, D/BN, 3*E);
    k_inproj<<<gin, 256>>>(x, ipw, ipb);
    k_scan1<<<(LANES*CCH)/256, 256>>>();
    k_carry<<<LANES/256, 256>>>(out + EMD);
    dim3 ge(M/BM, D/BN, E);
    k_mid<<<ge, 256>>>(mw, mb);
    k_ff1<<<ge, 256>>>(fw1, fb1);
    k_ff2<<<ge, 256>>>(fw2, fb2);
    k_ln<<<M, 256>>>(lnw, lnb, out);
}

// round 9
// speedup vs baseline: 1.1080x; 1.1080x over previous
#include <cuda_runtime.h>
#include <math.h>
#include <stdint.h>

#define E 4
#define DIN 256
#define D 256
#define NB 16
#define T 1024
#define M (NB*T)            // 16384 rows per expert
#define EMD ((size_t)E*M*D) // 64MB fp32

#define CCH 16              // scan chunks
#define CLEN (T/CCH)        // 64
#define LANES (E*NB*D)      // 8192

// Scratch (static device globals)
__device__ float g_ir[EMD];
__device__ float g_ii[EMD];
__device__ float g_o [EMD];
__device__ float g_out[EMD];
__device__ float g_fr[E*D], g_fi[E*D], g_gam[E*D];
__device__ float g_finr[LANES*CCH], g_fini[LANES*CCH];
__device__ float g_Sr[LANES*CCH],  g_Si[LANES*CCH];

// ---------------- tf32 tensor-core GEMM core -------------------------------------
// Block 128x64x32, double-buffered dynamic smem + register-staged prefetch.
// 256 threads = 8 warps (4m x 2n), warp tile 32x32. One __syncthreads per k-iter.
#define BM 128
#define BN 64
#define BKK 32
#define ASS 36   // 32 + 4 pad  (conflict-free a-frag reads: 36g mod 32 = 4g)
#define BSS 72   // 64 + 8 pad  (72tg mod 32 = 8tg)
#define A_BUF_W (BM*ASS)            // 4608 words
#define B_BUF_W (BKK*BSS)           // 2304 words
#define SMEM_BYTES ((2*A_BUF_W + 2*B_BUF_W)*4)   // 55296 B

__device__ __forceinline__ uint32_t f2tf(float f) {
    uint32_t u; asm("cvt.rna.tf32.f32 %0, %1;" : "=r"(u) : "f"(f)); return u;
}

template<int SGN>
__device__ __forceinline__ void gemm_mma(
    const float* __restrict__ A,   // M x 256 row-major
    const float* __restrict__ W,   // 256 x 256 row-major
    int m0, int n0, float (&acc)[2][4][4],
    uint32_t* __restrict__ As, uint32_t* __restrict__ Bs, int tid)
{
    const int lane = tid & 31, wid = tid >> 5;
    const int g = lane >> 2, tg = lane & 3;
    const int wm0 = (wid & 3) * 32, wn0 = (wid >> 2) * 32;

    // per-thread load coords
    int arow[4], acol[4], brow[2], bcol[2];
    #pragma unroll
    for (int i = 0; i < 4; i++) { int idx = tid + i*256; arow[i] = idx >> 3; acol[i] = (idx & 7)*4; }
    #pragma unroll
    for (int i = 0; i < 2; i++) { int idx = tid + i*256; brow[i] = idx >> 4; bcol[i] = (idx & 15)*4; }

    float4 ra[4], rb[2];
    #pragma unroll
    for (int i = 0; i < 4; i++)
        ra[i] = *(const float4*)(A + (size_t)(m0 + arow[i])*256 + acol[i]);
    #pragma unroll
    for (int i = 0; i < 2; i++) {
        float4 v = *(const float4*)(W + (size_t)brow[i]*256 + n0 + bcol[i]);
        if (SGN < 0) { v.x=-v.x; v.y=-v.y; v.z=-v.z; v.w=-v.w; }
        rb[i] = v;
    }
    __syncthreads();   // protect smem vs prior use
    int cur = 0;
    #pragma unroll
    for (int it = 0; it < 256/BKK; it++) {
        // store staged regs -> smem[cur]
        #pragma unroll
        for (int i = 0; i < 4; i++)
            *(uint4*)&As[cur*A_BUF_W + arow[i]*ASS + acol[i]] =
                make_uint4(f2tf(ra[i].x), f2tf(ra[i].y), f2tf(ra[i].z), f2tf(ra[i].w));
        #pragma unroll
        for (int i = 0; i < 2; i++)
            *(uint4*)&Bs[cur*B_BUF_W + brow[i]*BSS + bcol[i]] =
                make_uint4(f2tf(rb[i].x), f2tf(rb[i].y), f2tf(rb[i].z), f2tf(rb[i].w));
        __syncthreads();
        if (it < 256/BKK - 1) {
            int k0 = (it+1)*BKK;
            #pragma unroll
            for (int i = 0; i < 4; i++)
                ra[i] = *(const float4*)(A + (size_t)(m0 + arow[i])*256 + k0 + acol[i]);
            #pragma unroll
            for (int i = 0; i < 2; i++) {
                float4 v = *(const float4*)(W + (size_t)(k0 + brow[i])*256 + n0 + bcol[i]);
                if (SGN < 0) { v.x=-v.x; v.y=-v.y; v.z=-v.z; v.w=-v.w; }
                rb[i] = v;
            }
        }
        const uint32_t* Ab = As + cur*A_BUF_W;
        const uint32_t* Bb = Bs + cur*B_BUF_W;
        #pragma unroll
        for (int kk = 0; kk < BKK; kk += 8) {
            uint32_t a[2][4], b[4][2];
            #pragma unroll
            for (int mi = 0; mi < 2; mi++) {
                const uint32_t* base = Ab + (wm0 + mi*16 + g)*ASS + kk + tg;
                a[mi][0] = base[0];
                a[mi][1] = base[8*ASS];
                a[mi][2] = base[4];
                a[mi][3] = base[8*ASS + 4];
            }
            #pragma unroll
            for (int ni = 0; ni < 4; ni++) {
                const uint32_t* base = Bb + (kk + tg)*BSS + wn0 + ni*8 + g;
                b[ni][0] = base[0];
                b[ni][1] = base[4*BSS];
            }
            #pragma unroll
            for (int mi = 0; mi < 2; mi++)
                #pragma unroll
                for (int ni = 0; ni < 4; ni++)
                    asm volatile(
                        "mma.sync.aligned.m16n8k8.row.col.f32.tf32.tf32.f32 "
                        "{%0,%1,%2,%3}, {%4,%5,%6,%7}, {%8,%9}, {%0,%1,%2,%3};"
                        : "+f"(acc[mi][ni][0]), "+f"(acc[mi][ni][1]),
                          "+f"(acc[mi][ni][2]), "+f"(acc[mi][ni][3])
                        : "r"(a[mi][0]), "r"(a[mi][1]), "r"(a[mi][2]), "r"(a[mi][3]),
                          "r"(b[ni][0]), "r"(b[ni][1]));
        }
        cur ^= 1;
    }
}

// ---------------- params ---------------------------------------------------------
__global__ void k_params(const float* __restrict__ pl) {
    int i = blockIdx.x*blockDim.x + threadIdx.x;
    if (i < E*D) {
        float nu  = expf(pl[i]);
        float th  = expf(pl[E*D + i]);
        float gm  = expf(pl[2*E*D + i]);
        float mag = expf(-nu);
        g_fr[i]  = mag * cosf(th);
        g_fi[i]  = mag * sinf(th);
        g_gam[i] = gm;
    }
}

// ---------------- in_proj --------------------------------------------------------
__global__ void __launch_bounds__(256) k_inproj(
    const float* __restrict__ x, const float* __restrict__ w,
    const float* __restrict__ bias)
{
    extern __shared__ uint32_t dsm[];
    uint32_t* As = dsm;
    uint32_t* Bs = dsm + 2*A_BUF_W;
    int m0 = blockIdx.x*BM, n0 = blockIdx.y*BN;
    int ke = blockIdx.z; int k = ke / E; int e = ke % E;
    float acc[2][4][4] = {};
    gemm_mma<1>(x, w + (size_t)ke*DIN*D, m0, n0, acc, As, Bs, threadIdx.x);
    int lane = threadIdx.x & 31, wid = threadIdx.x >> 5;
    int g = lane >> 2, tg = lane & 3;
    int wm0 = (wid & 3) * 32, wn0 = (wid >> 2) * 32;
    float* dst = (k == 0) ? g_ir : (k == 1) ? g_ii : g_o;
    #pragma unroll
    for (int mi = 0; mi < 2; mi++) {
        int r0 = m0 + wm0 + mi*16 + g;
        #pragma unroll
        for (int ni = 0; ni < 4; ni++) {
            int c = n0 + wn0 + ni*8 + 2*tg;
            float b0 = bias[ke*D + c], b1 = bias[ke*D + c + 1];
            float s0 = (k < 2) ? g_gam[e*D + c]     : 1.0f;
            float s1 = (k < 2) ? g_gam[e*D + c + 1] : 1.0f;
            float2 v0 = make_float2((acc[mi][ni][0] + b0) * s0, (acc[mi][ni][1] + b1) * s1);
            float2 v1 = make_float2((acc[mi][ni][2] + b0) * s0, (acc[mi][ni][3] + b1) * s1);
            *(float2*)&dst[((size_t)e*M + r0    )*D + c] = v0;
            *(float2*)&dst[((size_t)e*M + r0 + 8)*D + c] = v1;
        }
    }
}

// ---------------- chunked LRU scan, float4 lanes ---------------------------------
// pass 1: local scan within each chunk (h0 = 0), in place, store chunk finals
__global__ void k_scan1() {
    int j = blockIdx.x*blockDim.x + threadIdx.x;   // float4 lane id
    int d4 = j % (D/4); int c = (j / (D/4)) % CCH; int eb = j / ((D/4)*CCH);
    int e = eb / NB; int d = d4*4;
    float4 fr = *(const float4*)(g_fr + e*D + d);
    float4 fi = *(const float4*)(g_fi + e*D + d);
    float4 hr = make_float4(0.f,0.f,0.f,0.f), hi = hr;
    size_t idx = ((size_t)eb*T + (size_t)c*CLEN)*D + d;
    #pragma unroll 4
    for (int t = 0; t < CLEN; t++, idx += D) {
        float4 ur = *(const float4*)(g_ir + idx);
        float4 ui = *(const float4*)(g_ii + idx);
        float4 nr, ni;
        nr.x = fmaf(fr.x, hr.x, fmaf(-fi.x, hi.x, ur.x));
        ni.x = fmaf(fr.x, hi.x, fmaf( fi.x, hr.x, ui.x));
        nr.y = fmaf(fr.y, hr.y, fmaf(-fi.y, hi.y, ur.y));
        ni.y = fmaf(fr.y, hi.y, fmaf( fi.y, hr.y, ui.y));
        nr.z = fmaf(fr.z, hr.z, fmaf(-fi.z, hi.z, ur.z));
        ni.z = fmaf(fr.z, hi.z, fmaf( fi.z, hr.z, ui.z));
        nr.w = fmaf(fr.w, hr.w, fmaf(-fi.w, hi.w, ur.w));
        ni.w = fmaf(fr.w, hi.w, fmaf( fi.w, hr.w, ui.w));
        hr = nr; hi = ni;
        *(float4*)(g_ir + idx) = hr;
        *(float4*)(g_ii + idx) = hi;
    }
    int fo = (eb*CCH + c)*D + d;
    *(float4*)(g_finr + fo) = hr;
    *(float4*)(g_fini + fo) = hi;
}

// pass 2: combine chunk finals -> end-of-chunk states S_c; emit hidden
__global__ void k_carry(float* __restrict__ hid) {
    int i = blockIdx.x*blockDim.x + threadIdx.x;   // (eb, d)
    int d = i % D; int eb = i / D; int e = eb / NB, b = eb % NB;
    float fr = g_fr[e*D+d], fi = g_fi[e*D+d];
    float pr = fr, pi = fi;                         // f^CLEN via 6 squarings
    #pragma unroll
    for (int s = 0; s < 6; s++) { float nr = pr*pr - pi*pi, ni2 = 2.f*pr*pi; pr = nr; pi = ni2; }
    float sr = 0.f, si = 0.f;
    #pragma unroll
    for (int c = 0; c < CCH; c++) {
        int j = (eb*CCH + c)*D + d;
        float tr = pr*sr - pi*si + g_finr[j];
        float ti = pr*si + pi*sr + g_fini[j];
        sr = tr; si = ti;
        g_Sr[j] = sr; g_Si[j] = si;
    }
    hid[b*(2*E*D) + e*D + d]         = sr;
    hid[b*(2*E*D) + E*D + e*D + d]   = si;
}

// pass 3: add carried-in state contribution to chunks 1..CCH-1
__global__ void k_scan2() {
    int j = blockIdx.x*blockDim.x + threadIdx.x;
    int d4 = j % (D/4); int c = (j / (D/4)) % CCH; int eb = j / ((D/4)*CCH);
    if (c == 0) return;
    int e = eb / NB; int d = d4*4;
    float4 fr = *(const float4*)(g_fr + e*D + d);
    float4 fi = *(const float4*)(g_fi + e*D + d);
    int so = (eb*CCH + (c-1))*D + d;
    float4 wr = *(const float4*)(g_Sr + so);
    float4 wi = *(const float4*)(g_Si + so);
    size_t idx = ((size_t)eb*T + (size_t)c*CLEN)*D + d;
    #pragma unroll 4
    for (int t = 0; t < CLEN; t++, idx += D) {
        float4 nr, ni;
        nr.x = wr.x*fr.x - wi.x*fi.x;  ni.x = wr.x*fi.x + wi.x*fr.x;
        nr.y = wr.y*fr.y - wi.y*fi.y;  ni.y = wr.y*fi.y + wi.y*fr.y;
        nr.z = wr.z*fr.z - wi.z*fi.z;  ni.z = wr.z*fi.z + wi.z*fr.z;
        nr.w = wr.w*fr.w - wi.w*fi.w;  ni.w = wr.w*fi.w + wi.w*fr.w;
        wr = nr; wi = ni;
        float4 vr = *(const float4*)(g_ir + idx);
        float4 vi = *(const float4*)(g_ii + idx);
        vr.x += wr.x; vr.y += wr.y; vr.z += wr.z; vr.w += wr.w;
        vi.x += wi.x; vi.y += wi.y; vi.z += wi.z; vi.w += wi.w;
        *(float4*)(g_ir + idx) = vr;
        *(float4*)(g_ii + idx) = vi;
    }
}

// ---------------- mid: out = out_r@W0 - out_i@W1 + (b0-b1) + o -------------------
__global__ void __launch_bounds__(256) k_mid(
    const float* __restrict__ mw, const float* __restrict__ mb)
{
    extern __shared__ uint32_t dsm[];
    uint32_t* As = dsm;
    uint32_t* Bs = dsm + 2*A_BUF_W;
    int m0 = blockIdx.x*BM, n0 = blockIdx.y*BN, e = blockIdx.z;
    float acc[2][4][4] = {};
    gemm_mma< 1>(g_ir + (size_t)e*M*D, mw + (size_t)e*D*D,     m0, n0, acc, As, Bs, threadIdx.x);
    gemm_mma<-1>(g_ii + (size_t)e*M*D, mw + (size_t)(E+e)*D*D, m0, n0, acc, As, Bs, threadIdx.x);
    int lane = threadIdx.x & 31, wid = threadIdx.x >> 5;
    int g = lane >> 2, tg = lane & 3;
    int wm0 = (wid & 3) * 32, wn0 = (wid >> 2) * 32;
    #pragma unroll
    for (int mi = 0; mi < 2; mi++) {
        int r0 = m0 + wm0 + mi*16 + g;
        #pragma unroll
        for (int ni = 0; ni < 4; ni++) {
            int c = n0 + wn0 + ni*8 + 2*tg;
            float b0 = mb[e*D+c]   - mb[(E+e)*D+c];
            float b1 = mb[e*D+c+1] - mb[(E+e)*D+c+1];
            size_t i0 = ((size_t)e*M + r0    )*D + c;
            size_t i1 = ((size_t)e*M + r0 + 8)*D + c;
            float2 o0 = *(const float2*)&g_o[i0];
            float2 o1 = *(const float2*)&g_o[i1];
            *(float2*)&g_out[i0] = make_float2(acc[mi][ni][0] + b0 + o0.x, acc[mi][ni][1] + b1 + o0.y);
            *(float2*)&g_out[i1] = make_float2(acc[mi][ni][2] + b0 + o1.x, acc[mi][ni][3] + b1 + o1.y);
        }
    }
}

// ---------------- ff1: h1 = gelu(out@W1 + b1)  (h1 -> g_ir) ----------------------
__device__ __forceinline__ float gelu_f(float v) {
    return 0.5f * v * (1.0f + erff(v * 0.70710678118654752f));
}

__global__ void __launch_bounds__(256) k_ff1(
    const float* __restrict__ w1, const float* __restrict__ b1)
{
    extern __shared__ uint32_t dsm[];
    uint32_t* As = dsm;
    uint32_t* Bs = dsm + 2*A_BUF_W;
    int m0 = blockIdx.x*BM, n0 = blockIdx.y*BN, e = blockIdx.z;
    float acc[2][4][4] = {};
    gemm_mma<1>(g_out + (size_t)e*M*D, w1 + (size_t)e*D*D, m0, n0, acc, As, Bs, threadIdx.x);
    int lane = threadIdx.x & 31, wid = threadIdx.x >> 5;
    int g = lane >> 2, tg = lane & 3;
    int wm0 = (wid & 3) * 32, wn0 = (wid >> 2) * 32;
    #pragma unroll
    for (int mi = 0; mi < 2; mi++) {
        int r0 = m0 + wm0 + mi*16 + g;
        #pragma unroll
        for (int ni = 0; ni < 4; ni++) {
            int c = n0 + wn0 + ni*8 + 2*tg;
            float b0 = b1[e*D+c], bb1 = b1[e*D+c+1];
            *(float2*)&g_ir[((size_t)e*M + r0    )*D + c] =
                make_float2(gelu_f(acc[mi][ni][0] + b0), gelu_f(acc[mi][ni][1] + bb1));
            *(float2*)&g_ir[((size_t)e*M + r0 + 8)*D + c] =
                make_float2(gelu_f(acc[mi][ni][2] + b0), gelu_f(acc[mi][ni][3] + bb1));
        }
    }
}

// ---------------- ff2: h2 = h1@W2 + b2 + out   (h2 -> g_ii) ----------------------
__global__ void __launch_bounds__(256) k_ff2(
    const float* __restrict__ w2, const float* __restrict__ b2)
{
    extern __shared__ uint32_t dsm[];
    uint32_t* As = dsm;
    uint32_t* Bs = dsm + 2*A_BUF_W;
    int m0 = blockIdx.x*BM, n0 = blockIdx.y*BN, e = blockIdx.z;
    float acc[2][4][4] = {};
    gemm_mma<1>(g_ir + (size_t)e*M*D, w2 + (size_t)e*D*D, m0, n0, acc, As, Bs, threadIdx.x);
    int lane = threadIdx.x & 31, wid = threadIdx.x >> 5;
    int g = lane >> 2, tg = lane & 3;
    int wm0 = (wid & 3) * 32, wn0 = (wid >> 2) * 32;
    #pragma unroll
    for (int mi = 0; mi < 2; mi++) {
        int r0 = m0 + wm0 + mi*16 + g;
        #pragma unroll
        for (int ni = 0; ni < 4; ni++) {
            int c = n0 + wn0 + ni*8 + 2*tg;
            float b0 = b2[e*D+c], b1v = b2[e*D+c+1];
            size_t i0 = ((size_t)e*M + r0    )*D + c;
            size_t i1 = ((size_t)e*M + r0 + 8)*D + c;
            float2 o0 = *(const float2*)&g_out[i0];
            float2 o1 = *(const float2*)&g_out[i1];
            *(float2*)&g_ii[i0] = make_float2(acc[mi][ni][0] + b0 + o0.x, acc[mi][ni][1] + b1v + o0.y);
            *(float2*)&g_ii[i1] = make_float2(acc[mi][ni][2] + b0 + o1.x, acc[mi][ni][3] + b1v + o1.y);
        }
    }
}

// ---------------- LayerNorm over (E,D) per (b,t) ---------------------------------
__global__ void k_ln(const float* __restrict__ lnw, const float* __restrict__ lnb,
                     float* __restrict__ out)
{
    int bt = blockIdx.x;          // 0..M-1
    int d  = threadIdx.x;         // 0..255
    float v[E]; float s = 0.f, s2 = 0.f;
    #pragma unroll
    for (int e = 0; e < E; e++) {
        float x = g_ii[((size_t)e*M + bt)*D + d];
        v[e] = x; s += x; s2 += x*x;
    }
    __shared__ float red[2][8];
    #pragma unroll
    for (int o = 16; o > 0; o >>= 1) {
        s  += __shfl_down_sync(0xffffffffu, s,  o);
        s2 += __shfl_down_sync(0xffffffffu, s2, o);
    }
    int lane = d & 31, w = d >> 5;
    if (lane == 0) { red[0][w] = s; red[1][w] = s2; }
    __syncthreads();
    if (w == 0) {
        s  = (lane < 8) ? red[0][lane] : 0.f;
        s2 = (lane < 8) ? red[1][lane] : 0.f;
        #pragma unroll
        for (int o = 4; o > 0; o >>= 1) {
            s  += __shfl_down_sync(0xffffffffu, s,  o);
            s2 += __shfl_down_sync(0xffffffffu, s2, o);
        }
        if (lane == 0) { red[0][0] = s; red[1][0] = s2; }
    }
    __syncthreads();
    float mean = red[0][0] * (1.0f/1024.0f);
    float var  = red[1][0] * (1.0f/1024.0f) - mean*mean;
    float rinv = rsqrtf(var + 1e-5f);
    #pragma unroll
    for (int e = 0; e < E; e++) {
        out[((size_t)e*M + bt)*D + d] =
            (v[e] - mean) * rinv * lnw[e*D + d] + lnb[e*D + d];
    }
}

// ---------------- launch ---------------------------------------------------------
extern "C" void kernel_launch(void* const* d_in, const int* in_sizes, int n_in,
                              void* d_out, int out_size)
{
    (void)in_sizes; (void)n_in; (void)out_size;
    const float* x   = (const float*)d_in[0];
    const float* ipw = (const float*)d_in[1];
    const float* ipb = (const float*)d_in[2];
    const float* pl  = (const float*)d_in[3];
    const float* mw  = (const float*)d_in[4];
    const float* mb  = (const float*)d_in[5];
    const float* fw1 = (const float*)d_in[6];
    const float* fb1 = (const float*)d_in[7];
    const float* fw2 = (const float*)d_in[8];
    const float* fb2 = (const float*)d_in[9];
    const float* lnw = (const float*)d_in[10];
    const float* lnb = (const float*)d_in[11];
    float* out = (float*)d_out;

    cudaFuncSetAttribute(k_inproj, cudaFuncAttributeMaxDynamicSharedMemorySize, SMEM_BYTES);
    cudaFuncSetAttribute(k_mid,    cudaFuncAttributeMaxDynamicSharedMemorySize, SMEM_BYTES);
    cudaFuncSetAttribute(k_ff1,    cudaFuncAttributeMaxDynamicSharedMemorySize, SMEM_BYTES);
    cudaFuncSetAttribute(k_ff2,    cudaFuncAttributeMaxDynamicSharedMemorySize, SMEM_BYTES);

    k_params<<<4, 256>>>(pl);
    dim3 gin(M/BM, D/BN, 3*E);
    k_inproj<<<gin, 256, SMEM_BYTES>>>(x, ipw, ipb);
    k_scan1<<<(LANES*CCH/4)/256, 256>>>();
    k_carry<<<LANES/256, 256>>>(out + EMD);
    k_scan2<<<(LANES*CCH/4)/256, 256>>>();
    dim3 ge(M/BM, D/BN, E);
    k_mid<<<ge, 256, SMEM_BYTES>>>(mw, mb);
    k_ff1<<<ge, 256, SMEM_BYTES>>>(fw1, fb1);
    k_ff2<<<ge, 256, SMEM_BYTES>>>(fw2, fb2);
    k_ln<<<M, 256>>>(lnw, lnb, out);
}

// round 10
// speedup vs baseline: 1.2464x; 1.1249x over previous
#include <cuda_runtime.h>
#include <math.h>
#include <stdint.h>

#define E 4
#define DIN 256
#define D 256
#define NB 16
#define T 1024
#define M (NB*T)            // 16384 rows per expert
#define EMD ((size_t)E*M*D) // 64MB fp32

#define CCH 16              // scan chunks
#define CLEN (T/CCH)        // 64
#define LANES (E*NB*D)      // 8192

// Scratch (static device globals)
__device__ float g_ir[EMD];
__device__ float g_ii[EMD];
__device__ float g_o [EMD];
__device__ float g_out[EMD];
__device__ float g_fr[E*D], g_fi[E*D], g_gam[E*D];
__device__ float g_finr[LANES*CCH], g_fini[LANES*CCH];
__device__ float g_Sr[LANES*CCH],  g_Si[LANES*CCH];

// ---------------- tf32 tensor-core GEMM core -------------------------------------
// Block 128x128x32, double-buffered dynamic smem + register-staged prefetch.
// 256 threads = 8 warps (2m x 4n), warp tile 64x32. One __syncthreads per k-iter.
#define BM 128
#define BN 128
#define BKK 32
#define ASS 36   // 32 + 4 pad  (a-frag reads: 36g mod 32 = 4g -> conflict-free)
#define BSS 136  // 128 + 8 pad (b-frag reads: 136tg mod 32 = 8tg -> conflict-free)
#define A_BUF_W (BM*ASS)            // 4608 words
#define B_BUF_W (BKK*BSS)           // 4352 words
#define SMEM_BYTES ((2*A_BUF_W + 2*B_BUF_W)*4)   // 71680 B

__device__ __forceinline__ uint32_t f2tf(float f) {
    uint32_t u; asm("cvt.rna.tf32.f32 %0, %1;" : "=r"(u) : "f"(f)); return u;
}

template<int SGN>
__device__ __forceinline__ void gemm_mma(
    const float* __restrict__ A,   // M x 256 row-major
    const float* __restrict__ W,   // 256 x 256 row-major
    int m0, int n0, float (&acc)[4][4][4],
    uint32_t* __restrict__ As, uint32_t* __restrict__ Bs, int tid)
{
    const int lane = tid & 31, wid = tid >> 5;
    const int g = lane >> 2, tg = lane & 3;
    const int wm0 = (wid & 1) * 64, wn0 = (wid >> 1) * 32;

    // per-thread load coords: A tile 128x32 (4 float4/thr), B tile 32x128 (4 float4/thr)
    int arow[4], acol[4], brow[4], bcol[4];
    #pragma unroll
    for (int i = 0; i < 4; i++) {
        int idx = tid + i*256;
        arow[i] = idx >> 3;  acol[i] = (idx & 7)*4;
        brow[i] = idx >> 5;  bcol[i] = (idx & 31)*4;
    }

    float4 ra[4], rb[4];
    #pragma unroll
    for (int i = 0; i < 4; i++)
        ra[i] = *(const float4*)(A + (size_t)(m0 + arow[i])*256 + acol[i]);
    #pragma unroll
    for (int i = 0; i < 4; i++) {
        float4 v = *(const float4*)(W + (size_t)brow[i]*256 + n0 + bcol[i]);
        if (SGN < 0) { v.x=-v.x; v.y=-v.y; v.z=-v.z; v.w=-v.w; }
        rb[i] = v;
    }
    __syncthreads();   // protect smem vs prior use
    int cur = 0;
    #pragma unroll
    for (int it = 0; it < 256/BKK; it++) {
        // store staged regs -> smem[cur]
        #pragma unroll
        for (int i = 0; i < 4; i++)
            *(uint4*)&As[cur*A_BUF_W + arow[i]*ASS + acol[i]] =
                make_uint4(f2tf(ra[i].x), f2tf(ra[i].y), f2tf(ra[i].z), f2tf(ra[i].w));
        #pragma unroll
        for (int i = 0; i < 4; i++)
            *(uint4*)&Bs[cur*B_BUF_W + brow[i]*BSS + bcol[i]] =
                make_uint4(f2tf(rb[i].x), f2tf(rb[i].y), f2tf(rb[i].z), f2tf(rb[i].w));
        __syncthreads();
        if (it < 256/BKK - 1) {
            int k0 = (it+1)*BKK;
            #pragma unroll
            for (int i = 0; i < 4; i++)
                ra[i] = *(const float4*)(A + (size_t)(m0 + arow[i])*256 + k0 + acol[i]);
            #pragma unroll
            for (int i = 0; i < 4; i++) {
                float4 v = *(const float4*)(W + (size_t)(k0 + brow[i])*256 + n0 + bcol[i]);
                if (SGN < 0) { v.x=-v.x; v.y=-v.y; v.z=-v.z; v.w=-v.w; }
                rb[i] = v;
            }
        }
        const uint32_t* Ab = As + cur*A_BUF_W;
        const uint32_t* Bb = Bs + cur*B_BUF_W;
        #pragma unroll
        for (int kk = 0; kk < BKK; kk += 8) {
            uint32_t a[4][4], b[4][2];
            #pragma unroll
            for (int mi = 0; mi < 4; mi++) {
                const uint32_t* base = Ab + (wm0 + mi*16 + g)*ASS + kk + tg;
                a[mi][0] = base[0];
                a[mi][1] = base[8*ASS];
                a[mi][2] = base[4];
                a[mi][3] = base[8*ASS + 4];
            }
            #pragma unroll
            for (int ni = 0; ni < 4; ni++) {
                const uint32_t* base = Bb + (kk + tg)*BSS + wn0 + ni*8 + g;
                b[ni][0] = base[0];
                b[ni][1] = base[4*BSS];
            }
            #pragma unroll
            for (int mi = 0; mi < 4; mi++)
                #pragma unroll
                for (int ni = 0; ni < 4; ni++)
                    asm volatile(
                        "mma.sync.aligned.m16n8k8.row.col.f32.tf32.tf32.f32 "
                        "{%0,%1,%2,%3}, {%4,%5,%6,%7}, {%8,%9}, {%0,%1,%2,%3};"
                        : "+f"(acc[mi][ni][0]), "+f"(acc[mi][ni][1]),
                          "+f"(acc[mi][ni][2]), "+f"(acc[mi][ni][3])
                        : "r"(a[mi][0]), "r"(a[mi][1]), "r"(a[mi][2]), "r"(a[mi][3]),
                          "r"(b[ni][0]), "r"(b[ni][1]));
        }
        cur ^= 1;
    }
}

// ---------------- params ---------------------------------------------------------
__global__ void k_params(const float* __restrict__ pl) {
    int i = blockIdx.x*blockDim.x + threadIdx.x;
    if (i < E*D) {
        float nu  = expf(pl[i]);
        float th  = expf(pl[E*D + i]);
        float gm  = expf(pl[2*E*D + i]);
        float mag = expf(-nu);
        g_fr[i]  = mag * cosf(th);
        g_fi[i]  = mag * sinf(th);
        g_gam[i] = gm;
    }
}

// ---------------- in_proj --------------------------------------------------------
__global__ void __launch_bounds__(256, 2) k_inproj(
    const float* __restrict__ x, const float* __restrict__ w,
    const float* __restrict__ bias)
{
    extern __shared__ uint32_t dsm[];
    uint32_t* As = dsm;
    uint32_t* Bs = dsm + 2*A_BUF_W;
    int m0 = blockIdx.x*BM, n0 = blockIdx.y*BN;
    int ke = blockIdx.z; int k = ke / E; int e = ke % E;
    float acc[4][4][4] = {};
    gemm_mma<1>(x, w + (size_t)ke*DIN*D, m0, n0, acc, As, Bs, threadIdx.x);
    int lane = threadIdx.x & 31, wid = threadIdx.x >> 5;
    int g = lane >> 2, tg = lane & 3;
    int wm0 = (wid & 1) * 64, wn0 = (wid >> 1) * 32;
    float* dst = (k == 0) ? g_ir : (k == 1) ? g_ii : g_o;
    #pragma unroll
    for (int mi = 0; mi < 4; mi++) {
        int r0 = m0 + wm0 + mi*16 + g;
        #pragma unroll
        for (int ni = 0; ni < 4; ni++) {
            int c = n0 + wn0 + ni*8 + 2*tg;
            float b0 = bias[ke*D + c], b1 = bias[ke*D + c + 1];
            float s0 = (k < 2) ? g_gam[e*D + c]     : 1.0f;
            float s1 = (k < 2) ? g_gam[e*D + c + 1] : 1.0f;
            float2 v0 = make_float2((acc[mi][ni][0] + b0) * s0, (acc[mi][ni][1] + b1) * s1);
            float2 v1 = make_float2((acc[mi][ni][2] + b0) * s0, (acc[mi][ni][3] + b1) * s1);
            *(float2*)&dst[((size_t)e*M + r0    )*D + c] = v0;
            *(float2*)&dst[((size_t)e*M + r0 + 8)*D + c] = v1;
        }
    }
}

// ---------------- chunked LRU scan, float4 lanes ---------------------------------
// pass 1: local scan within each chunk (h0 = 0), in place, store chunk finals
__global__ void k_scan1() {
    int j = blockIdx.x*blockDim.x + threadIdx.x;   // float4 lane id
    int d4 = j % (D/4); int c = (j / (D/4)) % CCH; int eb = j / ((D/4)*CCH);
    int e = eb / NB; int d = d4*4;
    float4 fr = *(const float4*)(g_fr + e*D + d);
    float4 fi = *(const float4*)(g_fi + e*D + d);
    float4 hr = make_float4(0.f,0.f,0.f,0.f), hi = hr;
    size_t idx = ((size_t)eb*T + (size_t)c*CLEN)*D + d;
    #pragma unroll 4
    for (int t = 0; t < CLEN; t++, idx += D) {
        float4 ur = *(const float4*)(g_ir + idx);
        float4 ui = *(const float4*)(g_ii + idx);
        float4 nr, ni;
        nr.x = fmaf(fr.x, hr.x, fmaf(-fi.x, hi.x, ur.x));
        ni.x = fmaf(fr.x, hi.x, fmaf( fi.x, hr.x, ui.x));
        nr.y = fmaf(fr.y, hr.y, fmaf(-fi.y, hi.y, ur.y));
        ni.y = fmaf(fr.y, hi.y, fmaf( fi.y, hr.y, ui.y));
        nr.z = fmaf(fr.z, hr.z, fmaf(-fi.z, hi.z, ur.z));
        ni.z = fmaf(fr.z, hi.z, fmaf( fi.z, hr.z, ui.z));
        nr.w = fmaf(fr.w, hr.w, fmaf(-fi.w, hi.w, ur.w));
        ni.w = fmaf(fr.w, hi.w, fmaf( fi.w, hr.w, ui.w));
        hr = nr; hi = ni;
        *(float4*)(g_ir + idx) = hr;
        *(float4*)(g_ii + idx) = hi;
    }
    int fo = (eb*CCH + c)*D + d;
    *(float4*)(g_finr + fo) = hr;
    *(float4*)(g_fini + fo) = hi;
}

// pass 2: combine chunk finals -> end-of-chunk states S_c; emit hidden
__global__ void k_carry(float* __restrict__ hid) {
    int i = blockIdx.x*blockDim.x + threadIdx.x;   // (eb, d)
    int d = i % D; int eb = i / D; int e = eb / NB, b = eb % NB;
    float fr = g_fr[e*D+d], fi = g_fi[e*D+d];
    float pr = fr, pi = fi;                         // f^CLEN via 6 squarings
    #pragma unroll
    for (int s = 0; s < 6; s++) { float nr = pr*pr - pi*pi, ni2 = 2.f*pr*pi; pr = nr; pi = ni2; }
    float sr = 0.f, si = 0.f;
    #pragma unroll
    for (int c = 0; c < CCH; c++) {
        int j = (eb*CCH + c)*D + d;
        float tr = pr*sr - pi*si + g_finr[j];
        float ti = pr*si + pi*sr + g_fini[j];
        sr = tr; si = ti;
        g_Sr[j] = sr; g_Si[j] = si;
    }
    hid[b*(2*E*D) + e*D + d]         = sr;
    hid[b*(2*E*D) + E*D + e*D + d]   = si;
}

// pass 3: add carried-in state contribution to chunks 1..CCH-1
__global__ void k_scan2() {
    int j = blockIdx.x*blockDim.x + threadIdx.x;
    int d4 = j % (D/4); int c = (j / (D/4)) % CCH; int eb = j / ((D/4)*CCH);
    if (c == 0) return;
    int e = eb / NB; int d = d4*4;
    float4 fr = *(const float4*)(g_fr + e*D + d);
    float4 fi = *(const float4*)(g_fi + e*D + d);
    int so = (eb*CCH + (c-1))*D + d;
    float4 wr = *(const float4*)(g_Sr + so);
    float4 wi = *(const float4*)(g_Si + so);
    size_t idx = ((size_t)eb*T + (size_t)c*CLEN)*D + d;
    #pragma unroll 4
    for (int t = 0; t < CLEN; t++, idx += D) {
        float4 nr, ni;
        nr.x = wr.x*fr.x - wi.x*fi.x;  ni.x = wr.x*fi.x + wi.x*fr.x;
        nr.y = wr.y*fr.y - wi.y*fi.y;  ni.y = wr.y*fi.y + wi.y*fr.y;
        nr.z = wr.z*fr.z - wi.z*fi.z;  ni.z = wr.z*fi.z + wi.z*fr.z;
        nr.w = wr.w*fr.w - wi.w*fi.w;  ni.w = wr.w*fi.w + wi.w*fr.w;
        wr = nr; wi = ni;
        float4 vr = *(const float4*)(g_ir + idx);
        float4 vi = *(const float4*)(g_ii + idx);
        vr.x += wr.x; vr.y += wr.y; vr.z += wr.z; vr.w += wr.w;
        vi.x += wi.x; vi.y += wi.y; vi.z += wi.z; vi.w += wi.w;
        *(float4*)(g_ir + idx) = vr;
        *(float4*)(g_ii + idx) = vi;
    }
}

// ---------------- mid: out = out_r@W0 - out_i@W1 + (b0-b1) + o -------------------
__global__ void __launch_bounds__(256, 2) k_mid(
    const float* __restrict__ mw, const float* __restrict__ mb)
{
    extern __shared__ uint32_t dsm[];
    uint32_t* As = dsm;
    uint32_t* Bs = dsm + 2*A_BUF_W;
    int m0 = blockIdx.x*BM, n0 = blockIdx.y*BN, e = blockIdx.z;
    float acc[4][4][4] = {};
    gemm_mma< 1>(g_ir + (size_t)e*M*D, mw + (size_t)e*D*D,     m0, n0, acc, As, Bs, threadIdx.x);
    gemm_mma<-1>(g_ii + (size_t)e*M*D, mw + (size_t)(E+e)*D*D, m0, n0, acc, As, Bs, threadIdx.x);
    int lane = threadIdx.x & 31, wid = threadIdx.x >> 5;
    int g = lane >> 2, tg = lane & 3;
    int wm0 = (wid & 1) * 64, wn0 = (wid >> 1) * 32;
    #pragma unroll
    for (int mi = 0; mi < 4; mi++) {
        int r0 = m0 + wm0 + mi*16 + g;
        #pragma unroll
        for (int ni = 0; ni < 4; ni++) {
            int c = n0 + wn0 + ni*8 + 2*tg;
            float b0 = mb[e*D+c]   - mb[(E+e)*D+c];
            float b1 = mb[e*D+c+1] - mb[(E+e)*D+c+1];
            size_t i0 = ((size_t)e*M + r0    )*D + c;
            size_t i1 = ((size_t)e*M + r0 + 8)*D + c;
            float2 o0 = *(const float2*)&g_o[i0];
            float2 o1 = *(const float2*)&g_o[i1];
            *(float2*)&g_out[i0] = make_float2(acc[mi][ni][0] + b0 + o0.x, acc[mi][ni][1] + b1 + o0.y);
            *(float2*)&g_out[i1] = make_float2(acc[mi][ni][2] + b0 + o1.x, acc[mi][ni][3] + b1 + o1.y);
        }
    }
}

// ---------------- ff1: h1 = gelu(out@W1 + b1)  (h1 -> g_ir) ----------------------
__device__ __forceinline__ float gelu_f(float v) {
    return 0.5f * v * (1.0f + erff(v * 0.70710678118654752f));
}

__global__ void __launch_bounds__(256, 2) k_ff1(
    const float* __restrict__ w1, const float* __restrict__ b1)
{
    extern __shared__ uint32_t dsm[];
    uint32_t* As = dsm;
    uint32_t* Bs = dsm + 2*A_BUF_W;
    int m0 = blockIdx.x*BM, n0 = blockIdx.y*BN, e = blockIdx.z;
    float acc[4][4][4] = {};
    gemm_mma<1>(g_out + (size_t)e*M*D, w1 + (size_t)e*D*D, m0, n0, acc, As, Bs, threadIdx.x);
    int lane = threadIdx.x & 31, wid = threadIdx.x >> 5;
    int g = lane >> 2, tg = lane & 3;
    int wm0 = (wid & 1) * 64, wn0 = (wid >> 1) * 32;
    #pragma unroll
    for (int mi = 0; mi < 4; mi++) {
        int r0 = m0 + wm0 + mi*16 + g;
        #pragma unroll
        for (int ni = 0; ni < 4; ni++) {
            int c = n0 + wn0 + ni*8 + 2*tg;
            float b0 = b1[e*D+c], bb1 = b1[e*D+c+1];
            *(float2*)&g_ir[((size_t)e*M + r0    )*D + c] =
                make_float2(gelu_f(acc[mi][ni][0] + b0), gelu_f(acc[mi][ni][1] + bb1));
            *(float2*)&g_ir[((size_t)e*M + r0 + 8)*D + c] =
                make_float2(gelu_f(acc[mi][ni][2] + b0), gelu_f(acc[mi][ni][3] + bb1));
        }
    }
}

// ---------------- ff2: h2 = h1@W2 + b2 + out   (h2 -> g_ii) ----------------------
__global__ void __launch_bounds__(256, 2) k_ff2(
    const float* __restrict__ w2, const float* __restrict__ b2)
{
    extern __shared__ uint32_t dsm[];
    uint32_t* As = dsm;
    uint32_t* Bs = dsm + 2*A_BUF_W;
    int m0 = blockIdx.x*BM, n0 = blockIdx.y*BN, e = blockIdx.z;
    float acc[4][4][4] = {};
    gemm_mma<1>(g_ir + (size_t)e*M*D, w2 + (size_t)e*D*D, m0, n0, acc, As, Bs, threadIdx.x);
    int lane = threadIdx.x & 31, wid = threadIdx.x >> 5;
    int g = lane >> 2, tg = lane & 3;
    int wm0 = (wid & 1) * 64, wn0 = (wid >> 1) * 32;
    #pragma unroll
    for (int mi = 0; mi < 4; mi++) {
        int r0 = m0 + wm0 + mi*16 + g;
        #pragma unroll
        for (int ni = 0; ni < 4; ni++) {
            int c = n0 + wn0 + ni*8 + 2*tg;
            float b0 = b2[e*D+c], b1v = b2[e*D+c+1];
            size_t i0 = ((size_t)e*M + r0    )*D + c;
            size_t i1 = ((size_t)e*M + r0 + 8)*D + c;
            float2 o0 = *(const float2*)&g_out[i0];
            float2 o1 = *(const float2*)&g_out[i1];
            *(float2*)&g_ii[i0] = make_float2(acc[mi][ni][0] + b0 + o0.x, acc[mi][ni][1] + b1v + o0.y);
            *(float2*)&g_ii[i1] = make_float2(acc[mi][ni][2] + b0 + o1.x, acc[mi][ni][3] + b1v + o1.y);
        }
    }
}

// ---------------- LayerNorm over (E,D) per (b,t) ---------------------------------
__global__ void k_ln(const float* __restrict__ lnw, const float* __restrict__ lnb,
                     float* __restrict__ out)
{
    int bt = blockIdx.x;          // 0..M-1
    int d  = threadIdx.x;         // 0..255
    float v[E]; float s = 0.f, s2 = 0.f;
    #pragma unroll
    for (int e = 0; e < E; e++) {
        float x = g_ii[((size_t)e*M + bt)*D + d];
        v[e] = x; s += x; s2 += x*x;
    }
    __shared__ float red[2][8];
    #pragma unroll
    for (int o = 16; o > 0; o >>= 1) {
        s  += __shfl_down_sync(0xffffffffu, s,  o);
        s2 += __shfl_down_sync(0xffffffffu, s2, o);
    }
    int lane = d & 31, w = d >> 5;
    if (lane == 0) { red[0][w] = s; red[1][w] = s2; }
    __syncthreads();
    if (w == 0) {
        s  = (lane < 8) ? red[0][lane] : 0.f;
        s2 = (lane < 8) ? red[1][lane] : 0.f;
        #pragma unroll
        for (int o = 4; o > 0; o >>= 1) {
            s  += __shfl_down_sync(0xffffffffu, s,  o);
            s2 += __shfl_down_sync(0xffffffffu, s2, o);
        }
        if (lane == 0) { red[0][0] = s; red[1][0] = s2; }
    }
    __syncthreads();
    float mean = red[0][0] * (1.0f/1024.0f);
    float var  = red[1][0] * (1.0f/1024.0f) - mean*mean;
    float rinv = rsqrtf(var + 1e-5f);
    #pragma unroll
    for (int e = 0; e < E; e++) {
        out[((size_t)e*M + bt)*D + d] =
            (v[e] - mean) * rinv * lnw[e*D + d] + lnb[e*D + d];
    }
}

// ---------------- launch ---------------------------------------------------------
extern "C" void kernel_launch(void* const* d_in, const int* in_sizes, int n_in,
                              void* d_out, int out_size)
{
    (void)in_sizes; (void)n_in; (void)out_size;
    const float* x   = (const float*)d_in[0];
    const float* ipw = (const float*)d_in[1];
    const float* ipb = (const float*)d_in[2];
    const float* pl  = (const float*)d_in[3];
    const float* mw  = (const float*)d_in[4];
    const float* mb  = (const float*)d_in[5];
    const float* fw1 = (const float*)d_in[6];
    const float* fb1 = (const float*)d_in[7];
    const float* fw2 = (const float*)d_in[8];
    const float* fb2 = (const float*)d_in[9];
    const float* lnw = (const float*)d_in[10];
    const float* lnb = (const float*)d_in[11];
    float* out = (float*)d_out;

    cudaFuncSetAttribute(k_inproj, cudaFuncAttributeMaxDynamicSharedMemorySize, SMEM_BYTES);
    cudaFuncSetAttribute(k_mid,    cudaFuncAttributeMaxDynamicSharedMemorySize, SMEM_BYTES);
    cudaFuncSetAttribute(k_ff1,    cudaFuncAttributeMaxDynamicSharedMemorySize, SMEM_BYTES);
    cudaFuncSetAttribute(k_ff2,    cudaFuncAttributeMaxDynamicSharedMemorySize, SMEM_BYTES);

    k_params<<<4, 256>>>(pl);
    dim3 gin(M/BM, D/BN, 3*E);
    k_inproj<<<gin, 256, SMEM_BYTES>>>(x, ipw, ipb);
    k_scan1<<<(LANES*CCH/4)/256, 256>>>();
    k_carry<<<LANES/256, 256>>>(out + EMD);
    k_scan2<<<(LANES*CCH/4)/256, 256>>>();
    dim3 ge(M/BM, D/BN, E);
    k_mid<<<ge, 256, SMEM_BYTES>>>(mw, mb);
    k_ff1<<<ge, 256, SMEM_BYTES>>>(fw1, fb1);
    k_ff2<<<ge, 256, SMEM_BYTES>>>(fw2, fb2);
    k_ln<<<M, 256>>>(lnw, lnb, out);
}

// round 13
// speedup vs baseline: 1.3995x; 1.1228x over previous
#include <cuda_runtime.h>
#include <cuda_fp16.h>
#include <math.h>
#include <stdint.h>

#define E 4
#define DIN 256
#define D 256
#define NB 16
#define T 1024
#define M (NB*T)            // 16384 rows per expert
#define EMD ((size_t)E*M*D) // 64MB fp32

#define CCH 16              // scan chunks
#define CLEN (T/CCH)        // 64
#define LANES (E*NB*D)      // 8192

// Scratch (static device globals)
__device__ float g_ir[EMD];
__device__ float g_ii[EMD];
__device__ float g_o [EMD];
__device__ float g_out[EMD];
__device__ float g_fr[E*D], g_fi[E*D], g_gam[E*D];
__device__ float g_finr[LANES*CCH], g_fini[LANES*CCH];
__device__ float g_Sr[LANES*CCH],  g_Si[LANES*CCH];
__device__ __half g_wt[28*256*256];  // transposed (+negated where needed) fp16 weights [u][n][k]

// ---------------- fp16 tensor-core GEMM core -------------------------------------
// Block 128x128x32(halves), double-buffered smem + register-staged prefetch.
// 256 threads = 8 warps (2m x 4n), warp tile 64x32. One __syncthreads per k-iter.
// Tiles stored as [row][kword] uint32 (=2 halves), stride 20 words (16 data + 4 pad).
#define RSTRIDE 20
#define TILE_W (128*RSTRIDE)   // 2560 words per tile buffer

__device__ __forceinline__ uint32_t h2pack(float a, float b) {
    __half2 h = __floats2half2_rn(a, b);
    return *(uint32_t*)&h;
}

// gemm_accum: C(128x128 at m0,n0) += A[m0.., :256] * Wh[n0.., :256]^T
// A fp32 row-major [M][256]; Wh fp16 row-major [256 n][256 k].
__device__ __forceinline__ void gemm_fp16(
    const float* __restrict__ A, const __half* __restrict__ Wh,
    int m0, int n0, float (&acc)[4][4][4],
    uint32_t* __restrict__ As, uint32_t* __restrict__ Bs, int tid)
{
    const int lane = tid & 31, wid = tid >> 5;
    const int g = lane >> 2, tg = lane & 3;
    const int wm0 = (wid & 1) * 64, wn0 = (wid >> 1) * 32;
    const int row = tid >> 1;            // 0..127
    const int hc  = (tid & 1) * 16;      // half-col base (0 or 16)
    const int wc  = (tid & 1) * 8;       // word-col base

    float4 ra[4]; uint4 rbu[2];
    #pragma unroll
    for (int i = 0; i < 4; i++)
        ra[i] = *(const float4*)(A + (size_t)(m0+row)*256 + hc + i*4);
    rbu[0] = *(const uint4*)(Wh + (size_t)(n0+row)*256 + hc);
    rbu[1] = *(const uint4*)(Wh + (size_t)(n0+row)*256 + hc + 8);

    __syncthreads();   // protect smem vs prior use
    int cur = 0;
    #pragma unroll
    for (int it = 0; it < 8; it++) {
        // stage regs -> smem[cur]
        *(uint4*)&As[cur*TILE_W + row*RSTRIDE + wc] = make_uint4(
            h2pack(ra[0].x, ra[0].y), h2pack(ra[0].z, ra[0].w),
            h2pack(ra[1].x, ra[1].y), h2pack(ra[1].z, ra[1].w));
        *(uint4*)&As[cur*TILE_W + row*RSTRIDE + wc + 4] = make_uint4(
            h2pack(ra[2].x, ra[2].y), h2pack(ra[2].z, ra[2].w),
            h2pack(ra[3].x, ra[3].y), h2pack(ra[3].z, ra[3].w));
        *(uint4*)&Bs[cur*TILE_W + row*RSTRIDE + wc]     = rbu[0];
        *(uint4*)&Bs[cur*TILE_W + row*RSTRIDE + wc + 4] = rbu[1];
        __syncthreads();
        if (it < 7) {
            int k0 = (it+1)*32;
            #pragma unroll
            for (int i = 0; i < 4; i++)
                ra[i] = *(const float4*)(A + (size_t)(m0+row)*256 + k0 + hc + i*4);
            rbu[0] = *(const uint4*)(Wh + (size_t)(n0+row)*256 + k0 + hc);
            rbu[1] = *(const uint4*)(Wh + (size_t)(n0+row)*256 + k0 + hc + 8);
        }
        const uint32_t* Ab = As + cur*TILE_W;
        const uint32_t* Bb = Bs + cur*TILE_W;
        #pragma unroll
        for (int kk = 0; kk < 2; kk++) {      // two K=16 steps
            int kb = kk*8;
            uint32_t a[4][4], b[4][2];
            #pragma unroll
            for (int mi = 0; mi < 4; mi++) {
                const uint32_t* base = Ab + (wm0 + mi*16 + g)*RSTRIDE + kb + tg;
                a[mi][0] = base[0];
                a[mi][1] = base[8*RSTRIDE];
                a[mi][2] = base[4];
                a[mi][3] = base[8*RSTRIDE + 4];
            }
            #pragma unroll
            for (int ni = 0; ni < 4; ni++) {
                const uint32_t* base = Bb + (wn0 + ni*8 + g)*RSTRIDE + kb + tg;
                b[ni][0] = base[0];
                b[ni][1] = base[4];
            }
            #pragma unroll
            for (int mi = 0; mi < 4; mi++)
                #pragma unroll
                for (int ni = 0; ni < 4; ni++)
                    asm volatile(
                        "mma.sync.aligned.m16n8k16.row.col.f32.f16.f16.f32 "
                        "{%0,%1,%2,%3}, {%4,%5,%6,%7}, {%8,%9}, {%0,%1,%2,%3};"
                        : "+f"(acc[mi][ni][0]), "+f"(acc[mi][ni][1]),
                          "+f"(acc[mi][ni][2]), "+f"(acc[mi][ni][3])
                        : "r"(a[mi][0]), "r"(a[mi][1]), "r"(a[mi][2]), "r"(a[mi][3]),
                          "r"(b[ni][0]), "r"(b[ni][1]));
        }
        cur ^= 1;
    }
}

// ---------------- params ---------------------------------------------------------
__global__ void k_params(const float* __restrict__ pl) {
    int i = blockIdx.x*blockDim.x + threadIdx.x;
    if (i < E*D) {
        float nu  = expf(pl[i]);
        float th  = expf(pl[E*D + i]);
        float gm  = expf(pl[2*E*D + i]);
        float mag = expf(-nu);
        g_fr[i]  = mag * cosf(th);
        g_fi[i]  = mag * sinf(th);
        g_gam[i] = gm;
    }
}

// ---------------- weight prep: transpose (+negate imag-mid) -> fp16 [u][n][k] ----
__global__ void k_wprep(const float* __restrict__ ipw, const float* __restrict__ mw,
                        const float* __restrict__ fw1, const float* __restrict__ fw2)
{
    int i = blockIdx.x*256 + threadIdx.x;       // over 28*65536
    int u = i >> 16; int nk = i & 65535;
    int n = nk >> 8, k = nk & 255;
    const float* src; float sgn = 1.f;
    if (u < 12)      src = ipw + (size_t)u*65536;
    else if (u < 16) src = mw  + (size_t)(u-12)*65536;
    else if (u < 20) { src = mw + (size_t)(u-16+4)*65536; sgn = -1.f; }
    else if (u < 24) src = fw1 + (size_t)(u-20)*65536;
    else             src = fw2 + (size_t)(u-24)*65536;
    g_wt[i] = __float2half(sgn * src[k*256 + n]);
}

// ---------------- in_proj --------------------------------------------------------
__global__ void __launch_bounds__(256, 2) k_inproj(
    const float* __restrict__ x, const float* __restrict__ bias)
{
    __shared__ uint32_t As[2*TILE_W];
    __shared__ uint32_t Bs[2*TILE_W];
    int m0 = blockIdx.x*128, n0 = blockIdx.y*128;
    int ke = blockIdx.z; int k = ke >> 2; int e = ke & 3;
    float acc[4][4][4] = {};
    gemm_fp16(x, g_wt + (size_t)ke*65536, m0, n0, acc, As, Bs, threadIdx.x);
    int lane = threadIdx.x & 31, wid = threadIdx.x >> 5;
    int g = lane >> 2, tg = lane & 3;
    int wm0 = (wid & 1) * 64, wn0 = (wid >> 1) * 32;
    float* dst = (k == 0) ? g_ir : (k == 1) ? g_ii : g_o;
    #pragma unroll
    for (int mi = 0; mi < 4; mi++) {
        int r0 = m0 + wm0 + mi*16 + g;
        #pragma unroll
        for (int ni = 0; ni < 4; ni++) {
            int c = n0 + wn0 + ni*8 + 2*tg;
            float b0 = bias[ke*D + c], b1 = bias[ke*D + c + 1];
            float s0 = (k < 2) ? g_gam[e*D + c]     : 1.0f;
            float s1 = (k < 2) ? g_gam[e*D + c + 1] : 1.0f;
            float2 v0 = make_float2((acc[mi][ni][0] + b0) * s0, (acc[mi][ni][1] + b1) * s1);
            float2 v1 = make_float2((acc[mi][ni][2] + b0) * s0, (acc[mi][ni][3] + b1) * s1);
            *(float2*)&dst[((size_t)e*M + r0    )*D + c] = v0;
            *(float2*)&dst[((size_t)e*M + r0 + 8)*D + c] = v1;
        }
    }
}

// ---------------- chunked LRU scan, float4 lanes ---------------------------------
__global__ void k_scan1() {
    int j = blockIdx.x*blockDim.x + threadIdx.x;
    int d4 = j % (D/4); int c = (j / (D/4)) % CCH; int eb = j / ((D/4)*CCH);
    int e = eb / NB; int d = d4*4;
    float4 fr = *(const float4*)(g_fr + e*D + d);
    float4 fi = *(const float4*)(g_fi + e*D + d);
    float4 hr = make_float4(0.f,0.f,0.f,0.f), hi = hr;
    size_t idx = ((size_t)eb*T + (size_t)c*CLEN)*D + d;
    #pragma unroll 4
    for (int t = 0; t < CLEN; t++, idx += D) {
        float4 ur = *(const float4*)(g_ir + idx);
        float4 ui = *(const float4*)(g_ii + idx);
        float4 nr, ni;
        nr.x = fmaf(fr.x, hr.x, fmaf(-fi.x, hi.x, ur.x));
        ni.x = fmaf(fr.x, hi.x, fmaf( fi.x, hr.x, ui.x));
        nr.y = fmaf(fr.y, hr.y, fmaf(-fi.y, hi.y, ur.y));
        ni.y = fmaf(fr.y, hi.y, fmaf( fi.y, hr.y, ui.y));
        nr.z = fmaf(fr.z, hr.z, fmaf(-fi.z, hi.z, ur.z));
        ni.z = fmaf(fr.z, hi.z, fmaf( fi.z, hr.z, ui.z));
        nr.w = fmaf(fr.w, hr.w, fmaf(-fi.w, hi.w, ur.w));
        ni.w = fmaf(fr.w, hi.w, fmaf( fi.w, hr.w, ui.w));
        hr = nr; hi = ni;
        *(float4*)(g_ir + idx) = hr;
        *(float4*)(g_ii + idx) = hi;
    }
    int fo = (eb*CCH + c)*D + d;
    *(float4*)(g_finr + fo) = hr;
    *(float4*)(g_fini + fo) = hi;
}

__global__ void k_carry(float* __restrict__ hid) {
    int i = blockIdx.x*blockDim.x + threadIdx.x;
    int d = i % D; int eb = i / D; int e = eb / NB, b = eb % NB;
    float fr = g_fr[e*D+d], fi = g_fi[e*D+d];
    float pr = fr, pi = fi;
    #pragma unroll
    for (int s = 0; s < 6; s++) { float nr = pr*pr - pi*pi, ni2 = 2.f*pr*pi; pr = nr; pi = ni2; }
    float sr = 0.f, si = 0.f;
    #pragma unroll
    for (int c = 0; c < CCH; c++) {
        int j = (eb*CCH + c)*D + d;
        float tr = pr*sr - pi*si + g_finr[j];
        float ti = pr*si + pi*sr + g_fini[j];
        sr = tr; si = ti;
        g_Sr[j] = sr; g_Si[j] = si;
    }
    hid[b*(2*E*D) + e*D + d]         = sr;
    hid[b*(2*E*D) + E*D + e*D + d]   = si;
}

__global__ void k_scan2() {
    int j = blockIdx.x*blockDim.x + threadIdx.x;
    int d4 = j % (D/4); int c = (j / (D/4)) % CCH; int eb = j / ((D/4)*CCH);
    if (c == 0) return;
    int e = eb / NB; int d = d4*4;
    float4 fr = *(const float4*)(g_fr + e*D + d);
    float4 fi = *(const float4*)(g_fi + e*D + d);
    int so = (eb*CCH + (c-1))*D + d;
    float4 wr = *(const float4*)(g_Sr + so);
    float4 wi = *(const float4*)(g_Si + so);
    size_t idx = ((size_t)eb*T + (size_t)c*CLEN)*D + d;
    #pragma unroll 4
    for (int t = 0; t < CLEN; t++, idx += D) {
        float4 nr, ni;
        nr.x = wr.x*fr.x - wi.x*fi.x;  ni.x = wr.x*fi.x + wi.x*fr.x;
        nr.y = wr.y*fr.y - wi.y*fi.y;  ni.y = wr.y*fi.y + wi.y*fr.y;
        nr.z = wr.z*fr.z - wi.z*fi.z;  ni.z = wr.z*fi.z + wi.z*fr.z;
        nr.w = wr.w*fr.w - wi.w*fi.w;  ni.w = wr.w*fi.w + wi.w*fr.w;
        wr = nr; wi = ni;
        float4 vr = *(const float4*)(g_ir + idx);
        float4 vi = *(const float4*)(g_ii + idx);
        vr.x += wr.x; vr.y += wr.y; vr.z += wr.z; vr.w += wr.w;
        vi.x += wi.x; vi.y += wi.y; vi.z += wi.z; vi.w += wi.w;
        *(float4*)(g_ir + idx) = vr;
        *(float4*)(g_ii + idx) = vi;
    }
}

// ---------------- mid: out = out_r@W0 + out_i@(-W1) + (b0-b1) + o ---------------
__global__ void __launch_bounds__(256, 2) k_mid(const float* __restrict__ mb)
{
    __shared__ uint32_t As[2*TILE_W];
    __shared__ uint32_t Bs[2*TILE_W];
    int m0 = blockIdx.x*128, n0 = blockIdx.y*128, e = blockIdx.z;
    float acc[4][4][4] = {};
    gemm_fp16(g_ir + (size_t)e*M*D, g_wt + (size_t)(12+e)*65536, m0, n0, acc, As, Bs, threadIdx.x);
    gemm_fp16(g_ii + (size_t)e*M*D, g_wt + (size_t)(16+e)*65536, m0, n0, acc, As, Bs, threadIdx.x);
    int lane = threadIdx.x & 31, wid = threadIdx.x >> 5;
    int g = lane >> 2, tg = lane & 3;
    int wm0 = (wid & 1) * 64, wn0 = (wid >> 1) * 32;
    #pragma unroll
    for (int mi = 0; mi < 4; mi++) {
        int r0 = m0 + wm0 + mi*16 + g;
        #pragma unroll
        for (int ni = 0; ni < 4; ni++) {
            int c = n0 + wn0 + ni*8 + 2*tg;
            float b0 = mb[e*D+c]   - mb[(E+e)*D+c];
            float b1 = mb[e*D+c+1] - mb[(E+e)*D+c+1];
            size_t i0 = ((size_t)e*M + r0    )*D + c;
            size_t i1 = ((size_t)e*M + r0 + 8)*D + c;
            float2 o0 = *(const float2*)&g_o[i0];
            float2 o1 = *(const float2*)&g_o[i1];
            *(float2*)&g_out[i0] = make_float2(acc[mi][ni][0] + b0 + o0.x, acc[mi][ni][1] + b1 + o0.y);
            *(float2*)&g_out[i1] = make_float2(acc[mi][ni][2] + b0 + o1.x, acc[mi][ni][3] + b1 + o1.y);
        }
    }
}

// ---------------- ff1: h1 = gelu(out@W1 + b1)  (h1 -> g_ir) ----------------------
__device__ __forceinline__ float gelu_f(float v) {
    return 0.5f * v * (1.0f + erff(v * 0.70710678118654752f));
}

__global__ void __launch_bounds__(256, 2) k_ff1(const float* __restrict__ b1)
{
    __shared__ uint32_t As[2*TILE_W];
    __shared__ uint32_t Bs[2*TILE_W];
    int m0 = blockIdx.x*128, n0 = blockIdx.y*128, e = blockIdx.z;
    float acc[4][4][4] = {};
    gemm_fp16(g_out + (size_t)e*M*D, g_wt + (size_t)(20+e)*65536, m0, n0, acc, As, Bs, threadIdx.x);
    int lane = threadIdx.x & 31, wid = threadIdx.x >> 5;
    int g = lane >> 2, tg = lane & 3;
    int wm0 = (wid & 1) * 64, wn0 = (wid >> 1) * 32;
    #pragma unroll
    for (int mi = 0; mi < 4; mi++) {
        int r0 = m0 + wm0 + mi*16 + g;
        #pragma unroll
        for (int ni = 0; ni < 4; ni++) {
            int c = n0 + wn0 + ni*8 + 2*tg;
            float b0 = b1[e*D+c], bb1 = b1[e*D+c+1];
            *(float2*)&g_ir[((size_t)e*M + r0    )*D + c] =
                make_float2(gelu_f(acc[mi][ni][0] + b0), gelu_f(acc[mi][ni][1] + bb1));
            *(float2*)&g_ir[((size_t)e*M + r0 + 8)*D + c] =
                make_float2(gelu_f(acc[mi][ni][2] + b0), gelu_f(acc[mi][ni][3] + bb1));
        }
    }
}

// ---------------- ff2: h2 = h1@W2 + b2 + out   (h2 -> g_ii) ----------------------
__global__ void __launch_bounds__(256, 2) k_ff2(const float* __restrict__ b2)
{
    __shared__ uint32_t As[2*TILE_W];
    __shared__ uint32_t Bs[2*TILE_W];
    int m0 = blockIdx.x*128, n0 = blockIdx.y*128, e = blockIdx.z;
    float acc[4][4][4] = {};
    gemm_fp16(g_ir + (size_t)e*M*D, g_wt + (size_t)(24+e)*65536, m0, n0, acc, As, Bs, threadIdx.x);
    int lane = threadIdx.x & 31, wid = threadIdx.x >> 5;
    int g = lane >> 2, tg = lane & 3;
    int wm0 = (wid & 1) * 64, wn0 = (wid >> 1) * 32;
    #pragma unroll
    for (int mi = 0; mi < 4; mi++) {
        int r0 = m0 + wm0 + mi*16 + g;
        #pragma unroll
        for (int ni = 0; ni < 4; ni++) {
            int c = n0 + wn0 + ni*8 + 2*tg;
            float b0 = b2[e*D+c], b1v = b2[e*D+c+1];
            size_t i0 = ((size_t)e*M + r0    )*D + c;
            size_t i1 = ((size_t)e*M + r0 + 8)*D + c;
            float2 o0 = *(const float2*)&g_out[i0];
            float2 o1 = *(const float2*)&g_out[i1];
            *(float2*)&g_ii[i0] = make_float2(acc[mi][ni][0] + b0 + o0.x, acc[mi][ni][1] + b1v + o0.y);
            *(float2*)&g_ii[i1] = make_float2(acc[mi][ni][2] + b0 + o1.x, acc[mi][ni][3] + b1v + o1.y);
        }
    }
}

// ---------------- LayerNorm over (E,D) per (b,t) ---------------------------------
__global__ void k_ln(const float* __restrict__ lnw, const float* __restrict__ lnb,
                     float* __restrict__ out)
{
    int bt = blockIdx.x;
    int d  = threadIdx.x;
    float v[E]; float s = 0.f, s2 = 0.f;
    #pragma unroll
    for (int e = 0; e < E; e++) {
        float x = g_ii[((size_t)e*M + bt)*D + d];
        v[e] = x; s += x; s2 += x*x;
    }
    __shared__ float red[2][8];
    #pragma unroll
    for (int o = 16; o > 0; o >>= 1) {
        s  += __shfl_down_sync(0xffffffffu, s,  o);
        s2 += __shfl_down_sync(0xffffffffu, s2, o);
    }
    int lane = d & 31, w = d >> 5;
    if (lane == 0) { red[0][w] = s; red[1][w] = s2; }
    __syncthreads();
    if (w == 0) {
        s  = (lane < 8) ? red[0][lane] : 0.f;
        s2 = (lane < 8) ? red[1][lane] : 0.f;
        #pragma unroll
        for (int o = 4; o > 0; o >>= 1) {
            s  += __shfl_down_sync(0xffffffffu, s,  o);
            s2 += __shfl_down_sync(0xffffffffu, s2, o);
        }
        if (lane == 0) { red[0][0] = s; red[1][0] = s2; }
    }
    __syncthreads();
    float mean = red[0][0] * (1.0f/1024.0f);
    float var  = red[1][0] * (1.0f/1024.0f) - mean*mean;
    float rinv = rsqrtf(var + 1e-5f);
    #pragma unroll
    for (int e = 0; e < E; e++) {
        out[((size_t)e*M + bt)*D + d] =
            (v[e] - mean) * rinv * lnw[e*D + d] + lnb[e*D + d];
    }
}

// ---------------- launch ---------------------------------------------------------
extern "C" void kernel_launch(void* const* d_in, const int* in_sizes, int n_in,
                              void* d_out, int out_size)
{
    (void)in_sizes; (void)n_in; (void)out_size;
    const float* x   = (const float*)d_in[0];
    const float* ipw = (const float*)d_in[1];
    const float* ipb = (const float*)d_in[2];
    const float* pl  = (const float*)d_in[3];
    const float* mw  = (const float*)d_in[4];
    const float* mb  = (const float*)d_in[5];
    const float* fw1 = (const float*)d_in[6];
    const float* fb1 = (const float*)d_in[7];
    const float* fw2 = (const float*)d_in[8];
    const float* fb2 = (const float*)d_in[9];
    const float* lnw = (const float*)d_in[10];
    const float* lnb = (const float*)d_in[11];
    float* out = (float*)d_out;

    k_params<<<4, 256>>>(pl);
    k_wprep<<<28*256, 256>>>(ipw, mw, fw1, fw2);
    dim3 gin(M/128, 2, 12);
    k_inproj<<<gin, 256>>>(x, ipb);
    k_scan1<<<(LANES*CCH/4)/256, 256>>>();
    k_carry<<<LANES/256, 256>>>(out + EMD);
    k_scan2<<<(LANES*CCH/4)/256, 256>>>();
    dim3 ge(M/128, 2, E);
    k_mid<<<ge, 256>>>(mb);
    k_ff1<<<ge, 256>>>(fb1);
    k_ff2<<<ge, 256>>>(fb2);
    k_ln<<<M, 256>>>(lnw, lnb, out);
}

// round 14
// speedup vs baseline: 1.6227x; 1.1595x over previous
#include <cuda_runtime.h>
#include <cuda_fp16.h>
#include <math.h>
#include <stdint.h>

#define E 4
#define DIN 256
#define D 256
#define NB 16
#define T 1024
#define M (NB*T)            // 16384 rows per expert
#define EMD ((size_t)E*M*D) // elems

#define CCH 32              // scan chunks
#define CLEN (T/CCH)        // 32
#define LANES (E*NB*D)      // 8192

// Scratch (static device globals)
__device__ __half g_irh[EMD];        // fp16: in_proj real -> scan -> mid A; then h1 (ff1->ff2)
__device__ __half g_iih[EMD];        // fp16: in_proj imag -> scan -> mid A
__device__ float  g_o  [EMD];        // fp32: in_proj o -> mid residual; then h2 (ff2->ln)
__device__ float  g_out[EMD];        // fp32: mid out -> ff1 A, ff2 residual
__device__ float g_fr[E*D], g_fi[E*D], g_gam[E*D];
__device__ float g_finr[LANES*CCH], g_fini[LANES*CCH];
__device__ float g_Sr[LANES*CCH],  g_Si[LANES*CCH];
__device__ __half g_wt[28*256*256];  // transposed (+negated where needed) fp16 weights [u][n][k]

// ---------------- helpers --------------------------------------------------------
__device__ __forceinline__ uint32_t h2pack(float a, float b) {
    __half2 h = __floats2half2_rn(a, b);
    return *(uint32_t*)&h;
}
__device__ __forceinline__ float2 h2f(uint32_t u) {
    __half2 h = *(__half2*)&u; return __half22float2(h);
}

// ---------------- fp16 tensor-core GEMM core -------------------------------------
// Block 128x128x32(halves), double-buffered smem + register-staged prefetch.
// 256 threads = 8 warps (2m x 4n), warp tile 64x32. One __syncthreads per k-iter.
// Tiles stored as [row][kword] uint32 (=2 halves), stride 20 words (16 data + 4 pad).
#define RSTRIDE 20
#define TILE_W (128*RSTRIDE)   // 2560 words per tile buffer

#define GEMM_COMPUTE_BODY() \
        const uint32_t* Ab = As + cur*TILE_W; \
        const uint32_t* Bb = Bs + cur*TILE_W; \
        _Pragma("unroll") \
        for (int kk = 0; kk < 2; kk++) { \
            int kb = kk*8; \
            uint32_t a[4][4], b[4][2]; \
            _Pragma("unroll") \
            for (int mi = 0; mi < 4; mi++) { \
                const uint32_t* base = Ab + (wm0 + mi*16 + g)*RSTRIDE + kb + tg; \
                a[mi][0] = base[0]; \
                a[mi][1] = base[8*RSTRIDE]; \
                a[mi][2] = base[4]; \
                a[mi][3] = base[8*RSTRIDE + 4]; \
            } \
            _Pragma("unroll") \
            for (int ni = 0; ni < 4; ni++) { \
                const uint32_t* base = Bb + (wn0 + ni*8 + g)*RSTRIDE + kb + tg; \
                b[ni][0] = base[0]; \
                b[ni][1] = base[4]; \
            } \
            _Pragma("unroll") \
            for (int mi = 0; mi < 4; mi++) \
                _Pragma("unroll") \
                for (int ni = 0; ni < 4; ni++) \
                    asm volatile( \
                        "mma.sync.aligned.m16n8k16.row.col.f32.f16.f16.f32 " \
                        "{%0,%1,%2,%3}, {%4,%5,%6,%7}, {%8,%9}, {%0,%1,%2,%3};" \
                        : "+f"(acc[mi][ni][0]), "+f"(acc[mi][ni][1]), \
                          "+f"(acc[mi][ni][2]), "+f"(acc[mi][ni][3]) \
                        : "r"(a[mi][0]), "r"(a[mi][1]), "r"(a[mi][2]), "r"(a[mi][3]), \
                          "r"(b[ni][0]), "r"(b[ni][1]));  \
        }

// A fp32 variant (cvt on staging)
__device__ __forceinline__ void gemm_fp16(
    const float* __restrict__ A, const __half* __restrict__ Wh,
    int m0, int n0, float (&acc)[4][4][4],
    uint32_t* __restrict__ As, uint32_t* __restrict__ Bs, int tid)
{
    const int lane = tid & 31, wid = tid >> 5;
    const int g = lane >> 2, tg = lane & 3;
    const int wm0 = (wid & 1) * 64, wn0 = (wid >> 1) * 32;
    const int row = tid >> 1;
    const int hc  = (tid & 1) * 16;
    const int wc  = (tid & 1) * 8;

    float4 ra[4]; uint4 rbu[2];
    #pragma unroll
    for (int i = 0; i < 4; i++)
        ra[i] = *(const float4*)(A + (size_t)(m0+row)*256 + hc + i*4);
    rbu[0] = *(const uint4*)(Wh + (size_t)(n0+row)*256 + hc);
    rbu[1] = *(const uint4*)(Wh + (size_t)(n0+row)*256 + hc + 8);

    __syncthreads();
    int cur = 0;
    #pragma unroll
    for (int it = 0; it < 8; it++) {
        *(uint4*)&As[cur*TILE_W + row*RSTRIDE + wc] = make_uint4(
            h2pack(ra[0].x, ra[0].y), h2pack(ra[0].z, ra[0].w),
            h2pack(ra[1].x, ra[1].y), h2pack(ra[1].z, ra[1].w));
        *(uint4*)&As[cur*TILE_W + row*RSTRIDE + wc + 4] = make_uint4(
            h2pack(ra[2].x, ra[2].y), h2pack(ra[2].z, ra[2].w),
            h2pack(ra[3].x, ra[3].y), h2pack(ra[3].z, ra[3].w));
        *(uint4*)&Bs[cur*TILE_W + row*RSTRIDE + wc]     = rbu[0];
        *(uint4*)&Bs[cur*TILE_W + row*RSTRIDE + wc + 4] = rbu[1];
        __syncthreads();
        if (it < 7) {
            int k0 = (it+1)*32;
            #pragma unroll
            for (int i = 0; i < 4; i++)
                ra[i] = *(const float4*)(A + (size_t)(m0+row)*256 + k0 + hc + i*4);
            rbu[0] = *(const uint4*)(Wh + (size_t)(n0+row)*256 + k0 + hc);
            rbu[1] = *(const uint4*)(Wh + (size_t)(n0+row)*256 + k0 + hc + 8);
        }
        GEMM_COMPUTE_BODY();
        cur ^= 1;
    }
}

// A fp16 variant (pure copies)
__device__ __forceinline__ void gemm_fp16h(
    const __half* __restrict__ Ah, const __half* __restrict__ Wh,
    int m0, int n0, float (&acc)[4][4][4],
    uint32_t* __restrict__ As, uint32_t* __restrict__ Bs, int tid)
{
    const int lane = tid & 31, wid = tid >> 5;
    const int g = lane >> 2, tg = lane & 3;
    const int wm0 = (wid & 1) * 64, wn0 = (wid >> 1) * 32;
    const int row = tid >> 1;
    const int hc  = (tid & 1) * 16;
    const int wc  = (tid & 1) * 8;

    uint4 rau[2], rbu[2];
    rau[0] = *(const uint4*)(Ah + (size_t)(m0+row)*256 + hc);
    rau[1] = *(const uint4*)(Ah + (size_t)(m0+row)*256 + hc + 8);
    rbu[0] = *(const uint4*)(Wh + (size_t)(n0+row)*256 + hc);
    rbu[1] = *(const uint4*)(Wh + (size_t)(n0+row)*256 + hc + 8);

    __syncthreads();
    int cur = 0;
    #pragma unroll
    for (int it = 0; it < 8; it++) {
        *(uint4*)&As[cur*TILE_W + row*RSTRIDE + wc]     = rau[0];
        *(uint4*)&As[cur*TILE_W + row*RSTRIDE + wc + 4] = rau[1];
        *(uint4*)&Bs[cur*TILE_W + row*RSTRIDE + wc]     = rbu[0];
        *(uint4*)&Bs[cur*TILE_W + row*RSTRIDE + wc + 4] = rbu[1];
        __syncthreads();
        if (it < 7) {
            int k0 = (it+1)*32;
            rau[0] = *(const uint4*)(Ah + (size_t)(m0+row)*256 + k0 + hc);
            rau[1] = *(const uint4*)(Ah + (size_t)(m0+row)*256 + k0 + hc + 8);
            rbu[0] = *(const uint4*)(Wh + (size_t)(n0+row)*256 + k0 + hc);
            rbu[1] = *(const uint4*)(Wh + (size_t)(n0+row)*256 + k0 + hc + 8);
        }
        GEMM_COMPUTE_BODY();
        cur ^= 1;
    }
}

// ---------------- params ---------------------------------------------------------
__global__ void k_params(const float* __restrict__ pl) {
    int i = blockIdx.x*blockDim.x + threadIdx.x;
    if (i < E*D) {
        float nu  = expf(pl[i]);
        float th  = expf(pl[E*D + i]);
        float gm  = expf(pl[2*E*D + i]);
        float mag = expf(-nu);
        g_fr[i]  = mag * cosf(th);
        g_fi[i]  = mag * sinf(th);
        g_gam[i] = gm;
    }
}

// ---------------- weight prep: transpose (+negate imag-mid) -> fp16 [u][n][k] ----
__global__ void k_wprep(const float* __restrict__ ipw, const float* __restrict__ mw,
                        const float* __restrict__ fw1, const float* __restrict__ fw2)
{
    int i = blockIdx.x*256 + threadIdx.x;       // over 28*65536
    int u = i >> 16; int nk = i & 65535;
    int n = nk >> 8, k = nk & 255;
    const float* src; float sgn = 1.f;
    if (u < 12)      src = ipw + (size_t)u*65536;
    else if (u < 16) src = mw  + (size_t)(u-12)*65536;
    else if (u < 20) { src = mw + (size_t)(u-16+4)*65536; sgn = -1.f; }
    else if (u < 24) src = fw1 + (size_t)(u-20)*65536;
    else             src = fw2 + (size_t)(u-24)*65536;
    g_wt[i] = __float2half(sgn * src[k*256 + n]);
}

// ---------------- in_proj --------------------------------------------------------
__global__ void __launch_bounds__(256, 2) k_inproj(
    const float* __restrict__ x, const float* __restrict__ bias)
{
    __shared__ uint32_t As[2*TILE_W];
    __shared__ uint32_t Bs[2*TILE_W];
    int m0 = blockIdx.x*128, n0 = blockIdx.y*128;
    int ke = blockIdx.z; int k = ke >> 2; int e = ke & 3;
    float acc[4][4][4] = {};
    gemm_fp16(x, g_wt + (size_t)ke*65536, m0, n0, acc, As, Bs, threadIdx.x);
    int lane = threadIdx.x & 31, wid = threadIdx.x >> 5;
    int g = lane >> 2, tg = lane & 3;
    int wm0 = (wid & 1) * 64, wn0 = (wid >> 1) * 32;
    #pragma unroll
    for (int mi = 0; mi < 4; mi++) {
        int r0 = m0 + wm0 + mi*16 + g;
        #pragma unroll
        for (int ni = 0; ni < 4; ni++) {
            int c = n0 + wn0 + ni*8 + 2*tg;
            float b0 = bias[ke*D + c], b1 = bias[ke*D + c + 1];
            size_t i0 = ((size_t)e*M + r0    )*D + c;
            size_t i1 = ((size_t)e*M + r0 + 8)*D + c;
            if (k == 2) {
                *(float2*)&g_o[i0] = make_float2(acc[mi][ni][0] + b0, acc[mi][ni][1] + b1);
                *(float2*)&g_o[i1] = make_float2(acc[mi][ni][2] + b0, acc[mi][ni][3] + b1);
            } else {
                float s0 = g_gam[e*D + c], s1 = g_gam[e*D + c + 1];
                __half* dh = (k == 0) ? g_irh : g_iih;
                *(uint32_t*)&dh[i0] = h2pack((acc[mi][ni][0] + b0)*s0, (acc[mi][ni][1] + b1)*s1);
                *(uint32_t*)&dh[i1] = h2pack((acc[mi][ni][2] + b0)*s0, (acc[mi][ni][3] + b1)*s1);
            }
        }
    }
}

// ---------------- chunked LRU scan, fp16 storage / fp32 math ---------------------
// mapping: j -> (eb, c, d4) with d4 over D/4 (4 halves per thread)
__global__ void k_scan1() {
    int j = blockIdx.x*blockDim.x + threadIdx.x;
    int d4 = j & 63; int c = (j >> 6) & (CCH-1); int eb = j >> 11;
    int e = eb / NB; int d = d4*4;
    float4 fr = *(const float4*)(g_fr + e*D + d);
    float4 fi = *(const float4*)(g_fi + e*D + d);
    float4 hr = make_float4(0.f,0.f,0.f,0.f), hi = hr;
    size_t idx = ((size_t)eb*T + (size_t)c*CLEN)*D + d;
    #pragma unroll 4
    for (int t = 0; t < CLEN; t++, idx += D) {
        uint2 urp = *(const uint2*)(g_irh + idx);
        uint2 uip = *(const uint2*)(g_iih + idx);
        float2 ur0 = h2f(urp.x), ur1 = h2f(urp.y);
        float2 ui0 = h2f(uip.x), ui1 = h2f(uip.y);
        float4 nr, ni;
        nr.x = fmaf(fr.x, hr.x, fmaf(-fi.x, hi.x, ur0.x));
        ni.x = fmaf(fr.x, hi.x, fmaf( fi.x, hr.x, ui0.x));
        nr.y = fmaf(fr.y, hr.y, fmaf(-fi.y, hi.y, ur0.y));
        ni.y = fmaf(fr.y, hi.y, fmaf( fi.y, hr.y, ui0.y));
        nr.z = fmaf(fr.z, hr.z, fmaf(-fi.z, hi.z, ur1.x));
        ni.z = fmaf(fr.z, hi.z, fmaf( fi.z, hr.z, ui1.x));
        nr.w = fmaf(fr.w, hr.w, fmaf(-fi.w, hi.w, ur1.y));
        ni.w = fmaf(fr.w, hi.w, fmaf( fi.w, hr.w, ui1.y));
        hr = nr; hi = ni;
        *(uint2*)(g_irh + idx) = make_uint2(h2pack(hr.x, hr.y), h2pack(hr.z, hr.w));
        *(uint2*)(g_iih + idx) = make_uint2(h2pack(hi.x, hi.y), h2pack(hi.z, hi.w));
    }
    int fo = (eb*CCH + c)*D + d;
    *(float4*)(g_finr + fo) = hr;
    *(float4*)(g_fini + fo) = hi;
}

// combine chunk finals -> end-of-chunk states S_c; emit hidden
__global__ void k_carry(float* __restrict__ hid) {
    int i = blockIdx.x*blockDim.x + threadIdx.x;
    int d = i % D; int eb = i / D; int e = eb / NB, b = eb % NB;
    float fr = g_fr[e*D+d], fi = g_fi[e*D+d];
    float pr = fr, pi = fi;                     // f^CLEN via 5 squarings (CLEN=32)
    #pragma unroll
    for (int s = 0; s < 5; s++) { float nr = pr*pr - pi*pi, ni2 = 2.f*pr*pi; pr = nr; pi = ni2; }
    float sr = 0.f, si = 0.f;
    #pragma unroll
    for (int c = 0; c < CCH; c++) {
        int j = (eb*CCH + c)*D + d;
        float tr = pr*sr - pi*si + g_finr[j];
        float ti = pr*si + pi*sr + g_fini[j];
        sr = tr; si = ti;
        g_Sr[j] = sr; g_Si[j] = si;
    }
    hid[b*(2*E*D) + e*D + d]         = sr;
    hid[b*(2*E*D) + E*D + e*D + d]   = si;
}

// add carried-in state contribution to chunks 1..CCH-1
__global__ void k_scan2() {
    int j = blockIdx.x*blockDim.x + threadIdx.x;
    int d4 = j & 63; int c = (j >> 6) & (CCH-1); int eb = j >> 11;
    if (c == 0) return;
    int e = eb / NB; int d = d4*4;
    float4 fr = *(const float4*)(g_fr + e*D + d);
    float4 fi = *(const float4*)(g_fi + e*D + d);
    int so = (eb*CCH + (c-1))*D + d;
    float4 wr = *(const float4*)(g_Sr + so);
    float4 wi = *(const float4*)(g_Si + so);
    size_t idx = ((size_t)eb*T + (size_t)c*CLEN)*D + d;
    #pragma unroll 4
    for (int t = 0; t < CLEN; t++, idx += D) {
        float4 nr, ni;
        nr.x = wr.x*fr.x - wi.x*fi.x;  ni.x = wr.x*fi.x + wi.x*fr.x;
        nr.y = wr.y*fr.y - wi.y*fi.y;  ni.y = wr.y*fi.y + wi.y*fr.y;
        nr.z = wr.z*fr.z - wi.z*fi.z;  ni.z = wr.z*fi.z + wi.z*fr.z;
        nr.w = wr.w*fr.w - wi.w*fi.w;  ni.w = wr.w*fi.w + wi.w*fr.w;
        wr = nr; wi = ni;
        uint2 vrp = *(const uint2*)(g_irh + idx);
        uint2 vip = *(const uint2*)(g_iih + idx);
        float2 vr0 = h2f(vrp.x), vr1 = h2f(vrp.y);
        float2 vi0 = h2f(vip.x), vi1 = h2f(vip.y);
        *(uint2*)(g_irh + idx) = make_uint2(h2pack(vr0.x + wr.x, vr0.y + wr.y),
                                            h2pack(vr1.x + wr.z, vr1.y + wr.w));
        *(uint2*)(g_iih + idx) = make_uint2(h2pack(vi0.x + wi.x, vi0.y + wi.y),
                                            h2pack(vi1.x + wi.z, vi1.y + wi.w));
    }
}

// ---------------- mid: out = out_r@W0 + out_i@(-W1) + (b0-b1) + o ---------------
__global__ void __launch_bounds__(256, 2) k_mid(const float* __restrict__ mb)
{
    __shared__ uint32_t As[2*TILE_W];
    __shared__ uint32_t Bs[2*TILE_W];
    int m0 = blockIdx.x*128, n0 = blockIdx.y*128, e = blockIdx.z;
    float acc[4][4][4] = {};
    gemm_fp16h(g_irh + (size_t)e*M*D, g_wt + (size_t)(12+e)*65536, m0, n0, acc, As, Bs, threadIdx.x);
    gemm_fp16h(g_iih + (size_t)e*M*D, g_wt + (size_t)(16+e)*65536, m0, n0, acc, As, Bs, threadIdx.x);
    int lane = threadIdx.x & 31, wid = threadIdx.x >> 5;
    int g = lane >> 2, tg = lane & 3;
    int wm0 = (wid & 1) * 64, wn0 = (wid >> 1) * 32;
    #pragma unroll
    for (int mi = 0; mi < 4; mi++) {
        int r0 = m0 + wm0 + mi*16 + g;
        #pragma unroll
        for (int ni = 0; ni < 4; ni++) {
            int c = n0 + wn0 + ni*8 + 2*tg;
            float b0 = mb[e*D+c]   - mb[(E+e)*D+c];
            float b1 = mb[e*D+c+1] - mb[(E+e)*D+c+1];
            size_t i0 = ((size_t)e*M + r0    )*D + c;
            size_t i1 = ((size_t)e*M + r0 + 8)*D + c;
            float2 o0 = *(const float2*)&g_o[i0];
            float2 o1 = *(const float2*)&g_o[i1];
            *(float2*)&g_out[i0] = make_float2(acc[mi][ni][0] + b0 + o0.x, acc[mi][ni][1] + b1 + o0.y);
            *(float2*)&g_out[i1] = make_float2(acc[mi][ni][2] + b0 + o1.x, acc[mi][ni][3] + b1 + o1.y);
        }
    }
}

// ---------------- ff1: h1 = gelu(out@W1 + b1)  (h1 -> g_irh, fp16) ---------------
__device__ __forceinline__ float gelu_f(float v) {
    return 0.5f * v * (1.0f + erff(v * 0.70710678118654752f));
}

__global__ void __launch_bounds__(256, 2) k_ff1(const float* __restrict__ b1)
{
    __shared__ uint32_t As[2*TILE_W];
    __shared__ uint32_t Bs[2*TILE_W];
    int m0 = blockIdx.x*128, n0 = blockIdx.y*128, e = blockIdx.z;
    float acc[4][4][4] = {};
    gemm_fp16(g_out + (size_t)e*M*D, g_wt + (size_t)(20+e)*65536, m0, n0, acc, As, Bs, threadIdx.x);
    int lane = threadIdx.x & 31, wid = threadIdx.x >> 5;
    int g = lane >> 2, tg = lane & 3;
    int wm0 = (wid & 1) * 64, wn0 = (wid >> 1) * 32;
    #pragma unroll
    for (int mi = 0; mi < 4; mi++) {
        int r0 = m0 + wm0 + mi*16 + g;
        #pragma unroll
        for (int ni = 0; ni < 4; ni++) {
            int c = n0 + wn0 + ni*8 + 2*tg;
            float b0 = b1[e*D+c], bb1 = b1[e*D+c+1];
            size_t i0 = ((size_t)e*M + r0    )*D + c;
            size_t i1 = ((size_t)e*M + r0 + 8)*D + c;
            *(uint32_t*)&g_irh[i0] = h2pack(gelu_f(acc[mi][ni][0] + b0), gelu_f(acc[mi][ni][1] + bb1));
            *(uint32_t*)&g_irh[i1] = h2pack(gelu_f(acc[mi][ni][2] + b0), gelu_f(acc[mi][ni][3] + bb1));
        }
    }
}

// ---------------- ff2: h2 = h1@W2 + b2 + out   (h2 -> g_o, fp32) -----------------
__global__ void __launch_bounds__(256, 2) k_ff2(const float* __restrict__ b2)
{
    __shared__ uint32_t As[2*TILE_W];
    __shared__ uint32_t Bs[2*TILE_W];
    int m0 = blockIdx.x*128, n0 = blockIdx.y*128, e = blockIdx.z;
    float acc[4][4][4] = {};
    gemm_fp16h(g_irh + (size_t)e*M*D, g_wt + (size_t)(24+e)*65536, m0, n0, acc, As, Bs, threadIdx.x);
    int lane = threadIdx.x & 31, wid = threadIdx.x >> 5;
    int g = lane >> 2, tg = lane & 3;
    int wm0 = (wid & 1) * 64, wn0 = (wid >> 1) * 32;
    #pragma unroll
    for (int mi = 0; mi < 4; mi++) {
        int r0 = m0 + wm0 + mi*16 + g;
        #pragma unroll
        for (int ni = 0; ni < 4; ni++) {
            int c = n0 + wn0 + ni*8 + 2*tg;
            float b0 = b2[e*D+c], b1v = b2[e*D+c+1];
            size_t i0 = ((size_t)e*M + r0    )*D + c;
            size_t i1 = ((size_t)e*M + r0 + 8)*D + c;
            float2 o0 = *(const float2*)&g_out[i0];
            float2 o1 = *(const float2*)&g_out[i1];
            *(float2*)&g_o[i0] = make_float2(acc[mi][ni][0] + b0 + o0.x, acc[mi][ni][1] + b1v + o0.y);
            *(float2*)&g_o[i1] = make_float2(acc[mi][ni][2] + b0 + o1.x, acc[mi][ni][3] + b1v + o1.y);
        }
    }
}

// ---------------- LayerNorm over (E,D) per (b,t) ---------------------------------
__global__ void k_ln(const float* __restrict__ lnw, const float* __restrict__ lnb,
                     float* __restrict__ out)
{
    int bt = blockIdx.x;
    int d  = threadIdx.x;
    float v[E]; float s = 0.f, s2 = 0.f;
    #pragma unroll
    for (int e = 0; e < E; e++) {
        float x = g_o[((size_t)e*M + bt)*D + d];
        v[e] = x; s += x; s2 += x*x;
    }
    __shared__ float red[2][8];
    #pragma unroll
    for (int o = 16; o > 0; o >>= 1) {
        s  += __shfl_down_sync(0xffffffffu, s,  o);
        s2 += __shfl_down_sync(0xffffffffu, s2, o);
    }
    int lane = d & 31, w = d >> 5;
    if (lane == 0) { red[0][w] = s; red[1][w] = s2; }
    __syncthreads();
    if (w == 0) {
        s  = (lane < 8) ? red[0][lane] : 0.f;
        s2 = (lane < 8) ? red[1][lane] : 0.f;
        #pragma unroll
        for (int o = 4; o > 0; o >>= 1) {
            s  += __shfl_down_sync(0xffffffffu, s,  o);
            s2 += __shfl_down_sync(0xffffffffu, s2, o);
        }
        if (lane == 0) { red[0][0] = s; red[1][0] = s2; }
    }
    __syncthreads();
    float mean = red[0][0] * (1.0f/1024.0f);
    float var  = red[1][0] * (1.0f/1024.0f) - mean*mean;
    float rinv = rsqrtf(var + 1e-5f);
    #pragma unroll
    for (int e = 0; e < E; e++) {
        out[((size_t)e*M + bt)*D + d] =
            (v[e] - mean) * rinv * lnw[e*D + d] + lnb[e*D + d];
    }
}

// ---------------- launch ---------------------------------------------------------
extern "C" void kernel_launch(void* const* d_in, const int* in_sizes, int n_in,
                              void* d_out, int out_size)
{
    (void)in_sizes; (void)n_in; (void)out_size;
    const float* x   = (const float*)d_in[0];
    const float* ipw = (const float*)d_in[1];
    const float* ipb = (const float*)d_in[2];
    const float* pl  = (const float*)d_in[3];
    const float* mw  = (const float*)d_in[4];
    const float* mb  = (const float*)d_in[5];
    const float* fw1 = (const float*)d_in[6];
    const float* fb1 = (const float*)d_in[7];
    const float* fw2 = (const float*)d_in[8];
    const float* fb2 = (const float*)d_in[9];
    const float* lnw = (const float*)d_in[10];
    const float* lnb = (const float*)d_in[11];
    float* out = (float*)d_out;

    k_params<<<4, 256>>>(pl);
    k_wprep<<<28*256, 256>>>(ipw, mw, fw1, fw2);
    dim3 gin(M/128, 2, 12);
    k_inproj<<<gin, 256>>>(x, ipb);
    k_scan1<<<(LANES*CCH/4)/256, 256>>>();
    k_carry<<<LANES/256, 256>>>(out + EMD);
    k_scan2<<<(LANES*CCH/4)/256, 256>>>();
    dim3 ge(M/128, 2, E);
    k_mid<<<ge, 256>>>(mb);
    k_ff1<<<ge, 256>>>(fb1);
    k_ff2<<<ge, 256>>>(fb2);
    k_ln<<<M, 256>>>(lnw, lnb, out);
}

// round 15
// speedup vs baseline: 1.7065x; 1.0516x over previous
#include <cuda_runtime.h>
#include <cuda_fp16.h>
#include <math.h>
#include <stdint.h>

#define E 4
#define DIN 256
#define D 256
#define NB 16
#define T 1024
#define M (NB*T)            // 16384 rows per expert
#define EMD ((size_t)E*M*D) // elems

#define CCH 32              // scan chunks
#define CLEN (T/CCH)        // 32
#define LANES (E*NB*D)      // 8192

// Scratch (static device globals)
__device__ __half g_irh[EMD];        // fp16: in_proj real -> scan -> mid A; then h1 (ff1->ff2)
__device__ __half g_iih[EMD];        // fp16: in_proj imag -> scan -> mid A
__device__ __half g_oh [EMD];        // fp16: in_proj o -> mid residual
__device__ __half g_outh[EMD];       // fp16: mid out -> ff1 A, ff2 residual
__device__ float  g_h2 [EMD];        // fp32: ff2 out -> ln
__device__ float g_fr[E*D], g_fi[E*D], g_gam[E*D];
__device__ float g_finr[LANES*CCH], g_fini[LANES*CCH];
__device__ float g_Sr[LANES*CCH],  g_Si[LANES*CCH];
__device__ __half g_wt[28*256*256];  // transposed (+negated where needed) fp16 weights [u][n][k]

// ---------------- helpers --------------------------------------------------------
__device__ __forceinline__ uint32_t h2pack(float a, float b) {
    __half2 h = __floats2half2_rn(a, b);
    return *(uint32_t*)&h;
}
__device__ __forceinline__ float2 h2f(uint32_t u) {
    __half2 h = *(__half2*)&u; return __half22float2(h);
}

// ---------------- fp16 tensor-core GEMM core -------------------------------------
// Block 128x128x32(halves), double-buffered smem + register-staged prefetch.
// 256 threads = 8 warps (2m x 4n), warp tile 64x32. One __syncthreads per k-iter.
// Tiles stored as [row][kword] uint32 (=2 halves), stride 20 words (16 data + 4 pad).
#define RSTRIDE 20
#define TILE_W (128*RSTRIDE)   // 2560 words per tile buffer

#define GEMM_COMPUTE_BODY() \
        const uint32_t* Ab = As + cur*TILE_W; \
        const uint32_t* Bb = Bs + cur*TILE_W; \
        _Pragma("unroll") \
        for (int kk = 0; kk < 2; kk++) { \
            int kb = kk*8; \
            uint32_t a[4][4], b[4][2]; \
            _Pragma("unroll") \
            for (int mi = 0; mi < 4; mi++) { \
                const uint32_t* base = Ab + (wm0 + mi*16 + g)*RSTRIDE + kb + tg; \
                a[mi][0] = base[0]; \
                a[mi][1] = base[8*RSTRIDE]; \
                a[mi][2] = base[4]; \
                a[mi][3] = base[8*RSTRIDE + 4]; \
            } \
            _Pragma("unroll") \
            for (int ni = 0; ni < 4; ni++) { \
                const uint32_t* base = Bb + (wn0 + ni*8 + g)*RSTRIDE + kb + tg; \
                b[ni][0] = base[0]; \
                b[ni][1] = base[4]; \
            } \
            _Pragma("unroll") \
            for (int mi = 0; mi < 4; mi++) \
                _Pragma("unroll") \
                for (int ni = 0; ni < 4; ni++) \
                    asm volatile( \
                        "mma.sync.aligned.m16n8k16.row.col.f32.f16.f16.f32 " \
                        "{%0,%1,%2,%3}, {%4,%5,%6,%7}, {%8,%9}, {%0,%1,%2,%3};" \
                        : "+f"(acc[mi][ni][0]), "+f"(acc[mi][ni][1]), \
                          "+f"(acc[mi][ni][2]), "+f"(acc[mi][ni][3]) \
                        : "r"(a[mi][0]), "r"(a[mi][1]), "r"(a[mi][2]), "r"(a[mi][3]), \
                          "r"(b[ni][0]), "r"(b[ni][1]));  \
        }

// A fp32 variant (cvt on staging)
__device__ __forceinline__ void gemm_fp16(
    const float* __restrict__ A, const __half* __restrict__ Wh,
    int m0, int n0, float (&acc)[4][4][4],
    uint32_t* __restrict__ As, uint32_t* __restrict__ Bs, int tid)
{
    const int lane = tid & 31, wid = tid >> 5;
    const int g = lane >> 2, tg = lane & 3;
    const int wm0 = (wid & 1) * 64, wn0 = (wid >> 1) * 32;
    const int row = tid >> 1;
    const int hc  = (tid & 1) * 16;
    const int wc  = (tid & 1) * 8;

    float4 ra[4]; uint4 rbu[2];
    #pragma unroll
    for (int i = 0; i < 4; i++)
        ra[i] = *(const float4*)(A + (size_t)(m0+row)*256 + hc + i*4);
    rbu[0] = *(const uint4*)(Wh + (size_t)(n0+row)*256 + hc);
    rbu[1] = *(const uint4*)(Wh + (size_t)(n0+row)*256 + hc + 8);

    __syncthreads();
    int cur = 0;
    #pragma unroll
    for (int it = 0; it < 8; it++) {
        *(uint4*)&As[cur*TILE_W + row*RSTRIDE + wc] = make_uint4(
            h2pack(ra[0].x, ra[0].y), h2pack(ra[0].z, ra[0].w),
            h2pack(ra[1].x, ra[1].y), h2pack(ra[1].z, ra[1].w));
        *(uint4*)&As[cur*TILE_W + row*RSTRIDE + wc + 4] = make_uint4(
            h2pack(ra[2].x, ra[2].y), h2pack(ra[2].z, ra[2].w),
            h2pack(ra[3].x, ra[3].y), h2pack(ra[3].z, ra[3].w));
        *(uint4*)&Bs[cur*TILE_W + row*RSTRIDE + wc]     = rbu[0];
        *(uint4*)&Bs[cur*TILE_W + row*RSTRIDE + wc + 4] = rbu[1];
        __syncthreads();
        if (it < 7) {
            int k0 = (it+1)*32;
            #pragma unroll
            for (int i = 0; i < 4; i++)
                ra[i] = *(const float4*)(A + (size_t)(m0+row)*256 + k0 + hc + i*4);
            rbu[0] = *(const uint4*)(Wh + (size_t)(n0+row)*256 + k0 + hc);
            rbu[1] = *(const uint4*)(Wh + (size_t)(n0+row)*256 + k0 + hc + 8);
        }
        GEMM_COMPUTE_BODY();
        cur ^= 1;
    }
}

// A fp16 variant (pure copies)
__device__ __forceinline__ void gemm_fp16h(
    const __half* __restrict__ Ah, const __half* __restrict__ Wh,
    int m0, int n0, float (&acc)[4][4][4],
    uint32_t* __restrict__ As, uint32_t* __restrict__ Bs, int tid)
{
    const int lane = tid & 31, wid = tid >> 5;
    const int g = lane >> 2, tg = lane & 3;
    const int wm0 = (wid & 1) * 64, wn0 = (wid >> 1) * 32;
    const int row = tid >> 1;
    const int hc  = (tid & 1) * 16;
    const int wc  = (tid & 1) * 8;

    uint4 rau[2], rbu[2];
    rau[0] = *(const uint4*)(Ah + (size_t)(m0+row)*256 + hc);
    rau[1] = *(const uint4*)(Ah + (size_t)(m0+row)*256 + hc + 8);
    rbu[0] = *(const uint4*)(Wh + (size_t)(n0+row)*256 + hc);
    rbu[1] = *(const uint4*)(Wh + (size_t)(n0+row)*256 + hc + 8);

    __syncthreads();
    int cur = 0;
    #pragma unroll
    for (int it = 0; it < 8; it++) {
        *(uint4*)&As[cur*TILE_W + row*RSTRIDE + wc]     = rau[0];
        *(uint4*)&As[cur*TILE_W + row*RSTRIDE + wc + 4] = rau[1];
        *(uint4*)&Bs[cur*TILE_W + row*RSTRIDE + wc]     = rbu[0];
        *(uint4*)&Bs[cur*TILE_W + row*RSTRIDE + wc + 4] = rbu[1];
        __syncthreads();
        if (it < 7) {
            int k0 = (it+1)*32;
            rau[0] = *(const uint4*)(Ah + (size_t)(m0+row)*256 + k0 + hc);
            rau[1] = *(const uint4*)(Ah + (size_t)(m0+row)*256 + k0 + hc + 8);
            rbu[0] = *(const uint4*)(Wh + (size_t)(n0+row)*256 + k0 + hc);
            rbu[1] = *(const uint4*)(Wh + (size_t)(n0+row)*256 + k0 + hc + 8);
        }
        GEMM_COMPUTE_BODY();
        cur ^= 1;
    }
}

// ---------------- params ---------------------------------------------------------
__global__ void k_params(const float* __restrict__ pl) {
    int i = blockIdx.x*blockDim.x + threadIdx.x;
    if (i < E*D) {
        float nu  = expf(pl[i]);
        float th  = expf(pl[E*D + i]);
        float gm  = expf(pl[2*E*D + i]);
        float mag = expf(-nu);
        g_fr[i]  = mag * cosf(th);
        g_fi[i]  = mag * sinf(th);
        g_gam[i] = gm;
    }
}

// ---------------- weight prep: transpose (+negate imag-mid) -> fp16 [u][n][k] ----
__global__ void k_wprep(const float* __restrict__ ipw, const float* __restrict__ mw,
                        const float* __restrict__ fw1, const float* __restrict__ fw2)
{
    int i = blockIdx.x*256 + threadIdx.x;       // over 28*65536
    int u = i >> 16; int nk = i & 65535;
    int n = nk >> 8, k = nk & 255;
    const float* src; float sgn = 1.f;
    if (u < 12)      src = ipw + (size_t)u*65536;
    else if (u < 16) src = mw  + (size_t)(u-12)*65536;
    else if (u < 20) { src = mw + (size_t)(u-16+4)*65536; sgn = -1.f; }
    else if (u < 24) src = fw1 + (size_t)(u-20)*65536;
    else             src = fw2 + (size_t)(u-24)*65536;
    g_wt[i] = __float2half(sgn * src[k*256 + n]);
}

// ---------------- in_proj --------------------------------------------------------
__global__ void __launch_bounds__(256, 2) k_inproj(
    const float* __restrict__ x, const float* __restrict__ bias)
{
    __shared__ uint32_t As[2*TILE_W];
    __shared__ uint32_t Bs[2*TILE_W];
    int m0 = blockIdx.x*128, n0 = blockIdx.y*128;
    int ke = blockIdx.z; int k = ke >> 2; int e = ke & 3;
    float acc[4][4][4] = {};
    gemm_fp16(x, g_wt + (size_t)ke*65536, m0, n0, acc, As, Bs, threadIdx.x);
    int lane = threadIdx.x & 31, wid = threadIdx.x >> 5;
    int g = lane >> 2, tg = lane & 3;
    int wm0 = (wid & 1) * 64, wn0 = (wid >> 1) * 32;
    __half* dh = (k == 0) ? g_irh : (k == 1) ? g_iih : g_oh;
    #pragma unroll
    for (int mi = 0; mi < 4; mi++) {
        int r0 = m0 + wm0 + mi*16 + g;
        #pragma unroll
        for (int ni = 0; ni < 4; ni++) {
            int c = n0 + wn0 + ni*8 + 2*tg;
            float b0 = bias[ke*D + c], b1 = bias[ke*D + c + 1];
            float s0 = 1.f, s1 = 1.f;
            if (k < 2) { s0 = g_gam[e*D + c]; s1 = g_gam[e*D + c + 1]; }
            size_t i0 = ((size_t)e*M + r0    )*D + c;
            size_t i1 = ((size_t)e*M + r0 + 8)*D + c;
            *(uint32_t*)&dh[i0] = h2pack((acc[mi][ni][0] + b0)*s0, (acc[mi][ni][1] + b1)*s1);
            *(uint32_t*)&dh[i1] = h2pack((acc[mi][ni][2] + b0)*s0, (acc[mi][ni][3] + b1)*s1);
        }
    }
}

// ---------------- chunked LRU scan, fp16 storage / fp32 math ---------------------
__global__ void k_scan1() {
    int j = blockIdx.x*blockDim.x + threadIdx.x;
    int d4 = j & 63; int c = (j >> 6) & (CCH-1); int eb = j >> 11;
    int e = eb / NB; int d = d4*4;
    float4 fr = *(const float4*)(g_fr + e*D + d);
    float4 fi = *(const float4*)(g_fi + e*D + d);
    float4 hr = make_float4(0.f,0.f,0.f,0.f), hi = hr;
    size_t idx = ((size_t)eb*T + (size_t)c*CLEN)*D + d;
    #pragma unroll 4
    for (int t = 0; t < CLEN; t++, idx += D) {
        uint2 urp = *(const uint2*)(g_irh + idx);
        uint2 uip = *(const uint2*)(g_iih + idx);
        float2 ur0 = h2f(urp.x), ur1 = h2f(urp.y);
        float2 ui0 = h2f(uip.x), ui1 = h2f(uip.y);
        float4 nr, ni;
        nr.x = fmaf(fr.x, hr.x, fmaf(-fi.x, hi.x, ur0.x));
        ni.x = fmaf(fr.x, hi.x, fmaf( fi.x, hr.x, ui0.x));
        nr.y = fmaf(fr.y, hr.y, fmaf(-fi.y, hi.y, ur0.y));
        ni.y = fmaf(fr.y, hi.y, fmaf( fi.y, hr.y, ui0.y));
        nr.z = fmaf(fr.z, hr.z, fmaf(-fi.z, hi.z, ur1.x));
        ni.z = fmaf(fr.z, hi.z, fmaf( fi.z, hr.z, ui1.x));
        nr.w = fmaf(fr.w, hr.w, fmaf(-fi.w, hi.w, ur1.y));
        ni.w = fmaf(fr.w, hi.w, fmaf( fi.w, hr.w, ui1.y));
        hr = nr; hi = ni;
        *(uint2*)(g_irh + idx) = make_uint2(h2pack(hr.x, hr.y), h2pack(hr.z, hr.w));
        *(uint2*)(g_iih + idx) = make_uint2(h2pack(hi.x, hi.y), h2pack(hi.z, hi.w));
    }
    int fo = (eb*CCH + c)*D + d;
    *(float4*)(g_finr + fo) = hr;
    *(float4*)(g_fini + fo) = hi;
}

__global__ void k_carry(float* __restrict__ hid) {
    int i = blockIdx.x*blockDim.x + threadIdx.x;
    int d = i % D; int eb = i / D; int e = eb / NB, b = eb % NB;
    float fr = g_fr[e*D+d], fi = g_fi[e*D+d];
    float pr = fr, pi = fi;                     // f^CLEN via 5 squarings (CLEN=32)
    #pragma unroll
    for (int s = 0; s < 5; s++) { float nr = pr*pr - pi*pi, ni2 = 2.f*pr*pi; pr = nr; pi = ni2; }
    float sr = 0.f, si = 0.f;
    #pragma unroll
    for (int c = 0; c < CCH; c++) {
        int j = (eb*CCH + c)*D + d;
        float tr = pr*sr - pi*si + g_finr[j];
        float ti = pr*si + pi*sr + g_fini[j];
        sr = tr; si = ti;
        g_Sr[j] = sr; g_Si[j] = si;
    }
    hid[b*(2*E*D) + e*D + d]         = sr;
    hid[b*(2*E*D) + E*D + e*D + d]   = si;
}

__global__ void k_scan2() {
    int j = blockIdx.x*blockDim.x + threadIdx.x;
    int d4 = j & 63; int c = (j >> 6) & (CCH-1); int eb = j >> 11;
    if (c == 0) return;
    int e = eb / NB; int d = d4*4;
    float4 fr = *(const float4*)(g_fr + e*D + d);
    float4 fi = *(const float4*)(g_fi + e*D + d);
    int so = (eb*CCH + (c-1))*D + d;
    float4 wr = *(const float4*)(g_Sr + so);
    float4 wi = *(const float4*)(g_Si + so);
    size_t idx = ((size_t)eb*T + (size_t)c*CLEN)*D + d;
    #pragma unroll 4
    for (int t = 0; t < CLEN; t++, idx += D) {
        float4 nr, ni;
        nr.x = wr.x*fr.x - wi.x*fi.x;  ni.x = wr.x*fi.x + wi.x*fr.x;
        nr.y = wr.y*fr.y - wi.y*fi.y;  ni.y = wr.y*fi.y + wi.y*fr.y;
        nr.z = wr.z*fr.z - wi.z*fi.z;  ni.z = wr.z*fi.z + wi.z*fr.z;
        nr.w = wr.w*fr.w - wi.w*fi.w;  ni.w = wr.w*fi.w + wi.w*fr.w;
        wr = nr; wi = ni;
        uint2 vrp = *(const uint2*)(g_irh + idx);
        uint2 vip = *(const uint2*)(g_iih + idx);
        float2 vr0 = h2f(vrp.x), vr1 = h2f(vrp.y);
        float2 vi0 = h2f(vip.x), vi1 = h2f(vip.y);
        *(uint2*)(g_irh + idx) = make_uint2(h2pack(vr0.x + wr.x, vr0.y + wr.y),
                                            h2pack(vr1.x + wr.z, vr1.y + wr.w));
        *(uint2*)(g_iih + idx) = make_uint2(h2pack(vi0.x + wi.x, vi0.y + wi.y),
                                            h2pack(vi1.x + wi.z, vi1.y + wi.w));
    }
}

// ---------------- mid: out = out_r@W0 + out_i@(-W1) + (b0-b1) + o ---------------
__global__ void __launch_bounds__(256, 2) k_mid(const float* __restrict__ mb)
{
    __shared__ uint32_t As[2*TILE_W];
    __shared__ uint32_t Bs[2*TILE_W];
    int m0 = blockIdx.x*128, n0 = blockIdx.y*128, e = blockIdx.z;
    float acc[4][4][4] = {};
    gemm_fp16h(g_irh + (size_t)e*M*D, g_wt + (size_t)(12+e)*65536, m0, n0, acc, As, Bs, threadIdx.x);
    gemm_fp16h(g_iih + (size_t)e*M*D, g_wt + (size_t)(16+e)*65536, m0, n0, acc, As, Bs, threadIdx.x);
    int lane = threadIdx.x & 31, wid = threadIdx.x >> 5;
    int g = lane >> 2, tg = lane & 3;
    int wm0 = (wid & 1) * 64, wn0 = (wid >> 1) * 32;
    #pragma unroll
    for (int mi = 0; mi < 4; mi++) {
        int r0 = m0 + wm0 + mi*16 + g;
        #pragma unroll
        for (int ni = 0; ni < 4; ni++) {
            int c = n0 + wn0 + ni*8 + 2*tg;
            float b0 = mb[e*D+c]   - mb[(E+e)*D+c];
            float b1 = mb[e*D+c+1] - mb[(E+e)*D+c+1];
            size_t i0 = ((size_t)e*M + r0    )*D + c;
            size_t i1 = ((size_t)e*M + r0 + 8)*D + c;
            float2 o0 = h2f(*(const uint32_t*)&g_oh[i0]);
            float2 o1 = h2f(*(const uint32_t*)&g_oh[i1]);
            *(uint32_t*)&g_outh[i0] = h2pack(acc[mi][ni][0] + b0 + o0.x, acc[mi][ni][1] + b1 + o0.y);
            *(uint32_t*)&g_outh[i1] = h2pack(acc[mi][ni][2] + b0 + o1.x, acc[mi][ni][3] + b1 + o1.y);
        }
    }
}

// ---------------- ff1: h1 = gelu(out@W1 + b1)  (h1 -> g_irh, fp16) ---------------
__device__ __forceinline__ float gelu_f(float v) {
    return 0.5f * v * (1.0f + erff(v * 0.70710678118654752f));
}

__global__ void __launch_bounds__(256, 2) k_ff1(const float* __restrict__ b1)
{
    __shared__ uint32_t As[2*TILE_W];
    __shared__ uint32_t Bs[2*TILE_W];
    int m0 = blockIdx.x*128, n0 = blockIdx.y*128, e = blockIdx.z;
    float acc[4][4][4] = {};
    gemm_fp16h(g_outh + (size_t)e*M*D, g_wt + (size_t)(20+e)*65536, m0, n0, acc, As, Bs, threadIdx.x);
    int lane = threadIdx.x & 31, wid = threadIdx.x >> 5;
    int g = lane >> 2, tg = lane & 3;
    int wm0 = (wid & 1) * 64, wn0 = (wid >> 1) * 32;
    #pragma unroll
    for (int mi = 0; mi < 4; mi++) {
        int r0 = m0 + wm0 + mi*16 + g;
        #pragma unroll
        for (int ni = 0; ni < 4; ni++) {
            int c = n0 + wn0 + ni*8 + 2*tg;
            float b0 = b1[e*D+c], bb1 = b1[e*D+c+1];
            size_t i0 = ((size_t)e*M + r0    )*D + c;
            size_t i1 = ((size_t)e*M + r0 + 8)*D + c;
            *(uint32_t*)&g_irh[i0] = h2pack(gelu_f(acc[mi][ni][0] + b0), gelu_f(acc[mi][ni][1] + bb1));
            *(uint32_t*)&g_irh[i1] = h2pack(gelu_f(acc[mi][ni][2] + b0), gelu_f(acc[mi][ni][3] + bb1));
        }
    }
}

// ---------------- ff2: h2 = h1@W2 + b2 + out   (h2 -> g_h2, fp32) ----------------
__global__ void __launch_bounds__(256, 2) k_ff2(const float* __restrict__ b2)
{
    __shared__ uint32_t As[2*TILE_W];
    __shared__ uint32_t Bs[2*TILE_W];
    int m0 = blockIdx.x*128, n0 = blockIdx.y*128, e = blockIdx.z;
    float acc[4][4][4] = {};
    gemm_fp16h(g_irh + (size_t)e*M*D, g_wt + (size_t)(24+e)*65536, m0, n0, acc, As, Bs, threadIdx.x);
    int lane = threadIdx.x & 31, wid = threadIdx.x >> 5;
    int g = lane >> 2, tg = lane & 3;
    int wm0 = (wid & 1) * 64, wn0 = (wid >> 1) * 32;
    #pragma unroll
    for (int mi = 0; mi < 4; mi++) {
        int r0 = m0 + wm0 + mi*16 + g;
        #pragma unroll
        for (int ni = 0; ni < 4; ni++) {
            int c = n0 + wn0 + ni*8 + 2*tg;
            float b0 = b2[e*D+c], b1v = b2[e*D+c+1];
            size_t i0 = ((size_t)e*M + r0    )*D + c;
            size_t i1 = ((size_t)e*M + r0 + 8)*D + c;
            float2 o0 = h2f(*(const uint32_t*)&g_outh[i0]);
            float2 o1 = h2f(*(const uint32_t*)&g_outh[i1]);
            *(float2*)&g_h2[i0] = make_float2(acc[mi][ni][0] + b0 + o0.x, acc[mi][ni][1] + b1v + o0.y);
            *(float2*)&g_h2[i1] = make_float2(acc[mi][ni][2] + b0 + o1.x, acc[mi][ni][3] + b1v + o1.y);
        }
    }
}

// ---------------- LayerNorm over (E,D) per (b,t) ---------------------------------
__global__ void k_ln(const float* __restrict__ lnw, const float* __restrict__ lnb,
                     float* __restrict__ out)
{
    int bt = blockIdx.x;
    int d  = threadIdx.x;
    float v[E]; float s = 0.f, s2 = 0.f;
    #pragma unroll
    for (int e = 0; e < E; e++) {
        float x = g_h2[((size_t)e*M + bt)*D + d];
        v[e] = x; s += x; s2 += x*x;
    }
    __shared__ float red[2][8];
    #pragma unroll
    for (int o = 16; o > 0; o >>= 1) {
        s  += __shfl_down_sync(0xffffffffu, s,  o);
        s2 += __shfl_down_sync(0xffffffffu, s2, o);
    }
    int lane = d & 31, w = d >> 5;
    if (lane == 0) { red[0][w] = s; red[1][w] = s2; }
    __syncthreads();
    if (w == 0) {
        s  = (lane < 8) ? red[0][lane] : 0.f;
        s2 = (lane < 8) ? red[1][lane] : 0.f;
        #pragma unroll
        for (int o = 4; o > 0; o >>= 1) {
            s  += __shfl_down_sync(0xffffffffu, s,  o);
            s2 += __shfl_down_sync(0xffffffffu, s2, o);
        }
        if (lane == 0) { red[0][0] = s; red[1][0] = s2; }
    }
    __syncthreads();
    float mean = red[0][0] * (1.0f/1024.0f);
    float var  = red[1][0] * (1.0f/1024.0f) - mean*mean;
    float rinv = rsqrtf(var + 1e-5f);
    #pragma unroll
    for (int e = 0; e < E; e++) {
        out[((size_t)e*M + bt)*D + d] =
            (v[e] - mean) * rinv * lnw[e*D + d] + lnb[e*D + d];
    }
}

// ---------------- launch ---------------------------------------------------------
extern "C" void kernel_launch(void* const* d_in, const int* in_sizes, int n_in,
                              void* d_out, int out_size)
{
    (void)in_sizes; (void)n_in; (void)out_size;
    const float* x   = (const float*)d_in[0];
    const float* ipw = (const float*)d_in[1];
    const float* ipb = (const float*)d_in[2];
    const float* pl  = (const float*)d_in[3];
    const float* mw  = (const float*)d_in[4];
    const float* mb  = (const float*)d_in[5];
    const float* fw1 = (const float*)d_in[6];
    const float* fb1 = (const float*)d_in[7];
    const float* fw2 = (const float*)d_in[8];
    const float* fb2 = (const float*)d_in[9];
    const float* lnw = (const float*)d_in[10];
    const float* lnb = (const float*)d_in[11];
    float* out = (float*)d_out;

    k_params<<<4, 256>>>(pl);
    k_wprep<<<28*256, 256>>>(ipw, mw, fw1, fw2);
    dim3 gin(M/128, 2, 12);
    k_inproj<<<gin, 256>>>(x, ipb);
    k_scan1<<<(LANES*CCH/4)/256, 256>>>();
    k_carry<<<LANES/256, 256>>>(out + EMD);
    k_scan2<<<(LANES*CCH/4)/256, 256>>>();
    dim3 ge(M/128, 2, E);
    k_mid<<<ge, 256>>>(mb);
    k_ff1<<<ge, 256>>>(fb1);
    k_ff2<<<ge, 256>>>(fb2);
    k_ln<<<M, 256>>>(lnw, lnb, out);
}

// round 16
// speedup vs baseline: 2.0765x; 1.2168x over previous
#include <cuda_runtime.h>
#include <cuda_fp16.h>
#include <math.h>
#include <stdint.h>

#define E 4
#define DIN 256
#define D 256
#define NB 16
#define T 1024
#define M (NB*T)            // 16384 rows per expert
#define EMD ((size_t)E*M*D) // elems

#define CCH 32              // scan chunks
#define CLEN (T/CCH)        // 32
#define LANES (E*NB*D)      // 8192

// Scratch (static device globals)
__device__ __half g_irh[EMD];        // fp16: in_proj real -> scan -> mid A; then h1 (ff1->ff2)
__device__ __half g_iih[EMD];        // fp16: in_proj imag -> scan -> mid A
__device__ __half g_oh [EMD];        // fp16: in_proj o -> mid residual
__device__ __half g_outh[EMD];       // fp16: mid out -> ff1 A, ff2 residual
__device__ float  g_h2 [EMD];        // fp32: ff2 out -> ln
__device__ __half g_xh [M*DIN];      // fp16 copy of x
__device__ float g_fr[E*D], g_fi[E*D], g_gam[E*D];
__device__ float g_finr[LANES*CCH], g_fini[LANES*CCH];
__device__ float g_Sr[LANES*CCH],  g_Si[LANES*CCH];
__device__ __half g_wt[28*256*256];  // transposed (+negated where needed) fp16 weights [u][n][k]

// ---------------- helpers --------------------------------------------------------
__device__ __forceinline__ uint32_t h2pack(float a, float b) {
    __half2 h = __floats2half2_rn(a, b);
    return *(uint32_t*)&h;
}
__device__ __forceinline__ float2 h2f(uint32_t u) {
    __half2 h = *(__half2*)&u; return __half22float2(h);
}
__device__ __forceinline__ void cp16(uint32_t dst, const void* src) {
    asm volatile("cp.async.cg.shared.global [%0], [%1], 16;" :: "r"(dst), "l"(src));
}
__device__ __forceinline__ void cp_commit() {
    asm volatile("cp.async.commit_group;" ::: "memory");
}
template<int N> __device__ __forceinline__ void cp_wait() {
    asm volatile("cp.async.wait_group %0;" :: "n"(N) : "memory");
}

// ---------------- fp16 tensor-core GEMM core, cp.async 3-stage -------------------
// Block 128x128x32(halves), 256 threads = 8 warps (2m x 4n), warp tile 64x32.
// Tiles [row][kword] stride 20 words; stage = A tile + B tile (20480 B); 3 stages.
#define RSTRIDE 20
#define TILE_WORDS (128*RSTRIDE)            // 2560
#define STAGE_WORDS (2*TILE_WORDS)          // 5120
#define SMEM_G (3*STAGE_WORDS*4)            // 61440 bytes

__device__ __forceinline__ void mma_tile(
    const uint32_t* __restrict__ Ab, const uint32_t* __restrict__ Bb,
    float (&acc)[4][4][4], int wm0, int wn0, int g, int tg)
{
    #pragma unroll
    for (int kk = 0; kk < 2; kk++) {
        int kb = kk*8;
        uint32_t a[4][4], b[4][2];
        #pragma unroll
        for (int mi = 0; mi < 4; mi++) {
            const uint32_t* base = Ab + (wm0 + mi*16 + g)*RSTRIDE + kb + tg;
            a[mi][0] = base[0];
            a[mi][1] = base[8*RSTRIDE];
            a[mi][2] = base[4];
            a[mi][3] = base[8*RSTRIDE + 4];
        }
        #pragma unroll
        for (int ni = 0; ni < 4; ni++) {
            const uint32_t* base = Bb + (wn0 + ni*8 + g)*RSTRIDE + kb + tg;
            b[ni][0] = base[0];
            b[ni][1] = base[4];
        }
        #pragma unroll
        for (int mi = 0; mi < 4; mi++)
            #pragma unroll
            for (int ni = 0; ni < 4; ni++)
                asm volatile(
                    "mma.sync.aligned.m16n8k16.row.col.f32.f16.f16.f32 "
                    "{%0,%1,%2,%3}, {%4,%5,%6,%7}, {%8,%9}, {%0,%1,%2,%3};"
                    : "+f"(acc[mi][ni][0]), "+f"(acc[mi][ni][1]),
                      "+f"(acc[mi][ni][2]), "+f"(acc[mi][ni][3])
                    : "r"(a[mi][0]), "r"(a[mi][1]), "r"(a[mi][2]), "r"(a[mi][3]),
                      "r"(b[ni][0]), "r"(b[ni][1]));
    }
}

__device__ __forceinline__ void gemm_ca(
    const __half* __restrict__ Ah, const __half* __restrict__ Wh,
    int m0, int n0, float (&acc)[4][4][4],
    uint32_t* __restrict__ dsm, int tid)
{
    const int lane = tid & 31, wid = tid >> 5;
    const int g = lane >> 2, tg = lane & 3;
    const int wm0 = (wid & 1) * 64, wn0 = (wid >> 1) * 32;
    const int row = tid >> 1;
    const int hc  = (tid & 1) * 16;
    const int wc  = (tid & 1) * 8;
    const uint32_t sbase = (uint32_t)__cvta_generic_to_shared(dsm);

    const __half* arow = Ah + (size_t)(m0+row)*256 + hc;
    const __half* brow = Wh + (size_t)(n0+row)*256 + hc;
    const uint32_t adst0 = sbase + (row*RSTRIDE + wc)*4;

    __syncthreads();   // protect smem vs prior use
    #pragma unroll
    for (int p = 0; p < 2; p++) {   // prefetch stages 0,1
        uint32_t as = adst0 + p*STAGE_WORDS*4;
        cp16(as,                      arow + p*32);
        cp16(as + 16,                 arow + p*32 + 8);
        cp16(as + TILE_WORDS*4,       brow + p*32);
        cp16(as + TILE_WORDS*4 + 16,  brow + p*32 + 8);
        cp_commit();
    }
    #pragma unroll
    for (int it = 0; it < 8; it++) {
        if (it < 7) cp_wait<1>(); else cp_wait<0>();
        __syncthreads();    // tile `it` visible to all; compute(it-1) done everywhere
        if (it + 2 < 8) {
            int s = (it+2) % 3;
            uint32_t as = adst0 + s*STAGE_WORDS*4;
            cp16(as,                      arow + (it+2)*32);
            cp16(as + 16,                 arow + (it+2)*32 + 8);
            cp16(as + TILE_WORDS*4,       brow + (it+2)*32);
            cp16(as + TILE_WORDS*4 + 16,  brow + (it+2)*32 + 8);
            cp_commit();
        }
        const uint32_t* Ab = dsm + (it%3)*STAGE_WORDS;
        const uint32_t* Bb = Ab + TILE_WORDS;
        mma_tile(Ab, Bb, acc, wm0, wn0, g, tg);
    }
}

// ---------------- params ---------------------------------------------------------
__global__ void k_params(const float* __restrict__ pl) {
    int i = blockIdx.x*blockDim.x + threadIdx.x;
    if (i < E*D) {
        float nu  = expf(pl[i]);
        float th  = expf(pl[E*D + i]);
        float gm  = expf(pl[2*E*D + i]);
        float mag = expf(-nu);
        g_fr[i]  = mag * cosf(th);
        g_fi[i]  = mag * sinf(th);
        g_gam[i] = gm;
    }
}

// ---------------- weight prep: transpose (+negate imag-mid) -> fp16 [u][n][k] ----
__global__ void k_wprep(const float* __restrict__ ipw, const float* __restrict__ mw,
                        const float* __restrict__ fw1, const float* __restrict__ fw2)
{
    int i = blockIdx.x*256 + threadIdx.x;       // over 28*65536
    int u = i >> 16; int nk = i & 65535;
    int n = nk >> 8, k = nk & 255;
    const float* src; float sgn = 1.f;
    if (u < 12)      src = ipw + (size_t)u*65536;
    else if (u < 16) src = mw  + (size_t)(u-12)*65536;
    else if (u < 20) { src = mw + (size_t)(u-16+4)*65536; sgn = -1.f; }
    else if (u < 24) src = fw1 + (size_t)(u-20)*65536;
    else             src = fw2 + (size_t)(u-24)*65536;
    g_wt[i] = __float2half(sgn * src[k*256 + n]);
}

// ---------------- x -> fp16 ------------------------------------------------------
__global__ void k_xh(const float* __restrict__ x) {
    int i = blockIdx.x*256 + threadIdx.x;       // over M*DIN/4
    float4 v = *(const float4*)(x + (size_t)i*4);
    *(uint2*)(g_xh + (size_t)i*4) = make_uint2(h2pack(v.x, v.y), h2pack(v.z, v.w));
}

// ---------------- in_proj --------------------------------------------------------
__global__ void __launch_bounds__(256, 2) k_inproj(const float* __restrict__ bias)
{
    extern __shared__ uint32_t dsm[];
    int m0 = blockIdx.x*128, n0 = blockIdx.y*128;
    int ke = blockIdx.z; int k = ke >> 2; int e = ke & 3;
    float acc[4][4][4] = {};
    gemm_ca(g_xh, g_wt + (size_t)ke*65536, m0, n0, acc, dsm, threadIdx.x);
    int lane = threadIdx.x & 31, wid = threadIdx.x >> 5;
    int g = lane >> 2, tg = lane & 3;
    int wm0 = (wid & 1) * 64, wn0 = (wid >> 1) * 32;
    __half* dh = (k == 0) ? g_irh : (k == 1) ? g_iih : g_oh;
    #pragma unroll
    for (int mi = 0; mi < 4; mi++) {
        int r0 = m0 + wm0 + mi*16 + g;
        #pragma unroll
        for (int ni = 0; ni < 4; ni++) {
            int c = n0 + wn0 + ni*8 + 2*tg;
            float b0 = bias[ke*D + c], b1 = bias[ke*D + c + 1];
            float s0 = 1.f, s1 = 1.f;
            if (k < 2) { s0 = g_gam[e*D + c]; s1 = g_gam[e*D + c + 1]; }
            size_t i0 = ((size_t)e*M + r0    )*D + c;
            size_t i1 = ((size_t)e*M + r0 + 8)*D + c;
            *(uint32_t*)&dh[i0] = h2pack((acc[mi][ni][0] + b0)*s0, (acc[mi][ni][1] + b1)*s1);
            *(uint32_t*)&dh[i1] = h2pack((acc[mi][ni][2] + b0)*s0, (acc[mi][ni][3] + b1)*s1);
        }
    }
}

// ---------------- chunked LRU scan, fp16 storage / fp32 math ---------------------
__global__ void k_scan1() {
    int j = blockIdx.x*blockDim.x + threadIdx.x;
    int d4 = j & 63; int c = (j >> 6) & (CCH-1); int eb = j >> 11;
    int e = eb / NB; int d = d4*4;
    float4 fr = *(const float4*)(g_fr + e*D + d);
    float4 fi = *(const float4*)(g_fi + e*D + d);
    float4 hr = make_float4(0.f,0.f,0.f,0.f), hi = hr;
    size_t idx = ((size_t)eb*T + (size_t)c*CLEN)*D + d;
    #pragma unroll 4
    for (int t = 0; t < CLEN; t++, idx += D) {
        uint2 urp = *(const uint2*)(g_irh + idx);
        uint2 uip = *(const uint2*)(g_iih + idx);
        float2 ur0 = h2f(urp.x), ur1 = h2f(urp.y);
        float2 ui0 = h2f(uip.x), ui1 = h2f(uip.y);
        float4 nr, ni;
        nr.x = fmaf(fr.x, hr.x, fmaf(-fi.x, hi.x, ur0.x));
        ni.x = fmaf(fr.x, hi.x, fmaf( fi.x, hr.x, ui0.x));
        nr.y = fmaf(fr.y, hr.y, fmaf(-fi.y, hi.y, ur0.y));
        ni.y = fmaf(fr.y, hi.y, fmaf( fi.y, hr.y, ui0.y));
        nr.z = fmaf(fr.z, hr.z, fmaf(-fi.z, hi.z, ur1.x));
        ni.z = fmaf(fr.z, hi.z, fmaf( fi.z, hr.z, ui1.x));
        nr.w = fmaf(fr.w, hr.w, fmaf(-fi.w, hi.w, ur1.y));
        ni.w = fmaf(fr.w, hi.w, fmaf( fi.w, hr.w, ui1.y));
        hr = nr; hi = ni;
        *(uint2*)(g_irh + idx) = make_uint2(h2pack(hr.x, hr.y), h2pack(hr.z, hr.w));
        *(uint2*)(g_iih + idx) = make_uint2(h2pack(hi.x, hi.y), h2pack(hi.z, hi.w));
    }
    int fo = (eb*CCH + c)*D + d;
    *(float4*)(g_finr + fo) = hr;
    *(float4*)(g_fini + fo) = hi;
}

__global__ void k_carry(float* __restrict__ hid) {
    int i = blockIdx.x*blockDim.x + threadIdx.x;
    int d = i % D; int eb = i / D; int e = eb / NB, b = eb % NB;
    float fr = g_fr[e*D+d], fi = g_fi[e*D+d];
    float pr = fr, pi = fi;                     // f^CLEN via 5 squarings (CLEN=32)
    #pragma unroll
    for (int s = 0; s < 5; s++) { float nr = pr*pr - pi*pi, ni2 = 2.f*pr*pi; pr = nr; pi = ni2; }
    float sr = 0.f, si = 0.f;
    #pragma unroll
    for (int c = 0; c < CCH; c++) {
        int j = (eb*CCH + c)*D + d;
        float tr = pr*sr - pi*si + g_finr[j];
        float ti = pr*si + pi*sr + g_fini[j];
        sr = tr; si = ti;
        g_Sr[j] = sr; g_Si[j] = si;
    }
    hid[b*(2*E*D) + e*D + d]         = sr;
    hid[b*(2*E*D) + E*D + e*D + d]   = si;
}

__global__ void k_scan2() {
    int j = blockIdx.x*blockDim.x + threadIdx.x;
    int d4 = j & 63; int c = (j >> 6) & (CCH-1); int eb = j >> 11;
    if (c == 0) return;
    int e = eb / NB; int d = d4*4;
    float4 fr = *(const float4*)(g_fr + e*D + d);
    float4 fi = *(const float4*)(g_fi + e*D + d);
    int so = (eb*CCH + (c-1))*D + d;
    float4 wr = *(const float4*)(g_Sr + so);
    float4 wi = *(const float4*)(g_Si + so);
    size_t idx = ((size_t)eb*T + (size_t)c*CLEN)*D + d;
    #pragma unroll 4
    for (int t = 0; t < CLEN; t++, idx += D) {
        float4 nr, ni;
        nr.x = wr.x*fr.x - wi.x*fi.x;  ni.x = wr.x*fi.x + wi.x*fr.x;
        nr.y = wr.y*fr.y - wi.y*fi.y;  ni.y = wr.y*fi.y + wi.y*fr.y;
        nr.z = wr.z*fr.z - wi.z*fi.z;  ni.z = wr.z*fi.z + wi.z*fr.z;
        nr.w = wr.w*fr.w - wi.w*fi.w;  ni.w = wr.w*fi.w + wi.w*fr.w;
        wr = nr; wi = ni;
        uint2 vrp = *(const uint2*)(g_irh + idx);
        uint2 vip = *(const uint2*)(g_iih + idx);
        float2 vr0 = h2f(vrp.x), vr1 = h2f(vrp.y);
        float2 vi0 = h2f(vip.x), vi1 = h2f(vip.y);
        *(uint2*)(g_irh + idx) = make_uint2(h2pack(vr0.x + wr.x, vr0.y + wr.y),
                                            h2pack(vr1.x + wr.z, vr1.y + wr.w));
        *(uint2*)(g_iih + idx) = make_uint2(h2pack(vi0.x + wi.x, vi0.y + wi.y),
                                            h2pack(vi1.x + wi.z, vi1.y + wi.w));
    }
}

// ---------------- mid: out = out_r@W0 + out_i@(-W1) + (b0-b1) + o ---------------
__global__ void __launch_bounds__(256, 2) k_mid(const float* __restrict__ mb)
{
    extern __shared__ uint32_t dsm[];
    int m0 = blockIdx.x*128, n0 = blockIdx.y*128, e = blockIdx.z;
    float acc[4][4][4] = {};
    gemm_ca(g_irh + (size_t)e*M*D, g_wt + (size_t)(12+e)*65536, m0, n0, acc, dsm, threadIdx.x);
    gemm_ca(g_iih + (size_t)e*M*D, g_wt + (size_t)(16+e)*65536, m0, n0, acc, dsm, threadIdx.x);
    int lane = threadIdx.x & 31, wid = threadIdx.x >> 5;
    int g = lane >> 2, tg = lane & 3;
    int wm0 = (wid & 1) * 64, wn0 = (wid >> 1) * 32;
    #pragma unroll
    for (int mi = 0; mi < 4; mi++) {
        int r0 = m0 + wm0 + mi*16 + g;
        #pragma unroll
        for (int ni = 0; ni < 4; ni++) {
            int c = n0 + wn0 + ni*8 + 2*tg;
            float b0 = mb[e*D+c]   - mb[(E+e)*D+c];
            float b1 = mb[e*D+c+1] - mb[(E+e)*D+c+1];
            size_t i0 = ((size_t)e*M + r0    )*D + c;
            size_t i1 = ((size_t)e*M + r0 + 8)*D + c;
            float2 o0 = h2f(*(const uint32_t*)&g_oh[i0]);
            float2 o1 = h2f(*(const uint32_t*)&g_oh[i1]);
            *(uint32_t*)&g_outh[i0] = h2pack(acc[mi][ni][0] + b0 + o0.x, acc[mi][ni][1] + b1 + o0.y);
            *(uint32_t*)&g_outh[i1] = h2pack(acc[mi][ni][2] + b0 + o1.x, acc[mi][ni][3] + b1 + o1.y);
        }
    }
}

// ---------------- ff1: h1 = gelu(out@W1 + b1)  (h1 -> g_irh, fp16) ---------------
__device__ __forceinline__ float gelu_f(float v) {
    return 0.5f * v * (1.0f + erff(v * 0.70710678118654752f));
}

__global__ void __launch_bounds__(256, 2) k_ff1(const float* __restrict__ b1)
{
    extern __shared__ uint32_t dsm[];
    int m0 = blockIdx.x*128, n0 = blockIdx.y*128, e = blockIdx.z;
    float acc[4][4][4] = {};
    gemm_ca(g_outh + (size_t)e*M*D, g_wt + (size_t)(20+e)*65536, m0, n0, acc, dsm, threadIdx.x);
    int lane = threadIdx.x & 31, wid = threadIdx.x >> 5;
    int g = lane >> 2, tg = lane & 3;
    int wm0 = (wid & 1) * 64, wn0 = (wid >> 1) * 32;
    #pragma unroll
    for (int mi = 0; mi < 4; mi++) {
        int r0 = m0 + wm0 + mi*16 + g;
        #pragma unroll
        for (int ni = 0; ni < 4; ni++) {
            int c = n0 + wn0 + ni*8 + 2*tg;
            float b0 = b1[e*D+c], bb1 = b1[e*D+c+1];
            size_t i0 = ((size_t)e*M + r0    )*D + c;
            size_t i1 = ((size_t)e*M + r0 + 8)*D + c;
            *(uint32_t*)&g_irh[i0] = h2pack(gelu_f(acc[mi][ni][0] + b0), gelu_f(acc[mi][ni][1] + bb1));
            *(uint32_t*)&g_irh[i1] = h2pack(gelu_f(acc[mi][ni][2] + b0), gelu_f(acc[mi][ni][3] + bb1));
        }
    }
}

// ---------------- ff2: h2 = h1@W2 + b2 + out   (h2 -> g_h2, fp32) ----------------
__global__ void __launch_bounds__(256, 2) k_ff2(const float* __restrict__ b2)
{
    extern __shared__ uint32_t dsm[];
    int m0 = blockIdx.x*128, n0 = blockIdx.y*128, e = blockIdx.z;
    float acc[4][4][4] = {};
    gemm_ca(g_irh + (size_t)e*M*D, g_wt + (size_t)(24+e)*65536, m0, n0, acc, dsm, threadIdx.x);
    int lane = threadIdx.x & 31, wid = threadIdx.x >> 5;
    int g = lane >> 2, tg = lane & 3;
    int wm0 = (wid & 1) * 64, wn0 = (wid >> 1) * 32;
    #pragma unroll
    for (int mi = 0; mi < 4; mi++) {
        int r0 = m0 + wm0 + mi*16 + g;
        #pragma unroll
        for (int ni = 0; ni < 4; ni++) {
            int c = n0 + wn0 + ni*8 + 2*tg;
            float b0 = b2[e*D+c], b1v = b2[e*D+c+1];
            size_t i0 = ((size_t)e*M + r0    )*D + c;
            size_t i1 = ((size_t)e*M + r0 + 8)*D + c;
            float2 o0 = h2f(*(const uint32_t*)&g_outh[i0]);
            float2 o1 = h2f(*(const uint32_t*)&g_outh[i1]);
            *(float2*)&g_h2[i0] = make_float2(acc[mi][ni][0] + b0 + o0.x, acc[mi][ni][1] + b1v + o0.y);
            *(float2*)&g_h2[i1] = make_float2(acc[mi][ni][2] + b0 + o1.x, acc[mi][ni][3] + b1v + o1.y);
        }
    }
}

// ---------------- LayerNorm over (E,D) per (b,t) ---------------------------------
__global__ void k_ln(const float* __restrict__ lnw, const float* __restrict__ lnb,
                     float* __restrict__ out)
{
    int bt = blockIdx.x;
    int d  = threadIdx.x;
    float v[E]; float s = 0.f, s2 = 0.f;
    #pragma unroll
    for (int e = 0; e < E; e++) {
        float x = g_h2[((size_t)e*M + bt)*D + d];
        v[e] = x; s += x; s2 += x*x;
    }
    __shared__ float red[2][8];
    #pragma unroll
    for (int o = 16; o > 0; o >>= 1) {
        s  += __shfl_down_sync(0xffffffffu, s,  o);
        s2 += __shfl_down_sync(0xffffffffu, s2, o);
    }
    int lane = d & 31, w = d >> 5;
    if (lane == 0) { red[0][w] = s; red[1][w] = s2; }
    __syncthreads();
    if (w == 0) {
        s  = (lane < 8) ? red[0][lane] : 0.f;
        s2 = (lane < 8) ? red[1][lane] : 0.f;
        #pragma unroll
        for (int o = 4; o > 0; o >>= 1) {
            s  += __shfl_down_sync(0xffffffffu, s,  o);
            s2 += __shfl_down_sync(0xffffffffu, s2, o);
        }
        if (lane == 0) { red[0][0] = s; red[1][0] = s2; }
    }
    __syncthreads();
    float mean = red[0][0] * (1.0f/1024.0f);
    float var  = red[1][0] * (1.0f/1024.0f) - mean*mean;
    float rinv = rsqrtf(var + 1e-5f);
    #pragma unroll
    for (int e = 0; e < E; e++) {
        out[((size_t)e*M + bt)*D + d] =
            (v[e] - mean) * rinv * lnw[e*D + d] + lnb[e*D + d];
    }
}

// ---------------- launch ---------------------------------------------------------
extern "C" void kernel_launch(void* const* d_in, const int* in_sizes, int n_in,
                              void* d_out, int out_size)
{
    (void)in_sizes; (void)n_in; (void)out_size;
    const float* x   = (const float*)d_in[0];
    const float* ipw = (const float*)d_in[1];
    const float* ipb = (const float*)d_in[2];
    const float* pl  = (const float*)d_in[3];
    const float* mw  = (const float*)d_in[4];
    const float* mb  = (const float*)d_in[5];
    const float* fw1 = (const float*)d_in[6];
    const float* fb1 = (const float*)d_in[7];
    const float* fw2 = (const float*)d_in[8];
    const float* fb2 = (const float*)d_in[9];
    const float* lnw = (const float*)d_in[10];
    const float* lnb = (const float*)d_in[11];
    float* out = (float*)d_out;

    cudaFuncSetAttribute(k_inproj, cudaFuncAttributeMaxDynamicSharedMemorySize, SMEM_G);
    cudaFuncSetAttribute(k_mid,    cudaFuncAttributeMaxDynamicSharedMemorySize, SMEM_G);
    cudaFuncSetAttribute(k_ff1,    cudaFuncAttributeMaxDynamicSharedMemorySize, SMEM_G);
    cudaFuncSetAttribute(k_ff2,    cudaFuncAttributeMaxDynamicSharedMemorySize, SMEM_G);

    k_params<<<4, 256>>>(pl);
    k_wprep<<<28*256, 256>>>(ipw, mw, fw1, fw2);
    k_xh<<<(M*DIN/4)/256, 256>>>(x);
    dim3 gin(M/128, 2, 12);
    k_inproj<<<gin, 256, SMEM_G>>>(ipb);
    k_scan1<<<(LANES*CCH/4)/256, 256>>>();
    k_carry<<<LANES/256, 256>>>(out + EMD);
    k_scan2<<<(LANES*CCH/4)/256, 256>>>();
    dim3 ge(M/128, 2, E);
    k_mid<<<ge, 256, SMEM_G>>>(mb);
    k_ff1<<<ge, 256, SMEM_G>>>(fb1);
    k_ff2<<<ge, 256, SMEM_G>>>(fb2);
    k_ln<<<M, 256>>>(lnw, lnb, out);
}

// round 17
// speedup vs baseline: 2.1005x; 1.0115x over previous
#include <cuda_runtime.h>
#include <cuda_fp16.h>
#include <math.h>
#include <stdint.h>

#define E 4
#define DIN 256
#define D 256
#define NB 16
#define T 1024
#define M (NB*T)            // 16384 rows per expert
#define EMD ((size_t)E*M*D) // elems

#define CCH 32              // scan chunks
#define CLEN (T/CCH)        // 32
#define LANES (E*NB*D)      // 8192

// Scratch (static device globals)
__device__ __half g_irh[EMD];        // fp16: in_proj real -> scan -> mid A; then h1 (ff1->ff2)
__device__ __half g_iih[EMD];        // fp16: in_proj imag -> scan -> mid A
__device__ __half g_oh [EMD];        // fp16: in_proj o -> mid residual
__device__ __half g_outh[EMD];       // fp16: mid out -> ff1 A, ff2 residual
__device__ float  g_h2 [EMD];        // fp32: ff2 out -> ln
__device__ __half g_xh [M*DIN];      // fp16 copy of x
__device__ float g_fr[E*D], g_fi[E*D], g_gam[E*D];
__device__ float g_finr[LANES*CCH], g_fini[LANES*CCH];
__device__ float g_Sr[LANES*CCH],  g_Si[LANES*CCH];
__device__ __half g_wt[28*256*256];  // transposed (+negated where needed) fp16 weights [u][n][k]

// ---------------- helpers --------------------------------------------------------
__device__ __forceinline__ uint32_t h2pack(float a, float b) {
    __half2 h = __floats2half2_rn(a, b);
    return *(uint32_t*)&h;
}
__device__ __forceinline__ float2 h2f(uint32_t u) {
    __half2 h = *(__half2*)&u; return __half22float2(h);
}
__device__ __forceinline__ void cp16(uint32_t dst, const void* src) {
    asm volatile("cp.async.cg.shared.global [%0], [%1], 16;" :: "r"(dst), "l"(src));
}
__device__ __forceinline__ void cp_commit() {
    asm volatile("cp.async.commit_group;" ::: "memory");
}
template<int N> __device__ __forceinline__ void cp_wait() {
    asm volatile("cp.async.wait_group %0;" :: "n"(N) : "memory");
}

// ---------------- fp16 tensor-core GEMM core, cp.async 3-stage -------------------
// Block 128x128x32(halves), 256 threads = 8 warps (2m x 4n), warp tile 64x32.
// Streaming tiles [row][kword] stride 20 words; stage = A tile + B tile; 3 stages.
#define RSTRIDE 20
#define TILE_WORDS (128*RSTRIDE)            // 2560
#define STAGE_WORDS (2*TILE_WORDS)          // 5120
#define SMEM_G (3*STAGE_WORDS*4)            // 61440 bytes

// A-resident layout (k_inproj): full 128x256-half A tile, stride 132 words
#define A_RSTRIDE 132
#define A_WORDS (128*A_RSTRIDE)             // 16896 words = 67584 B
#define SMEM_IP ((A_WORDS + 3*TILE_WORDS)*4) // 98304 B

template<int AST>
__device__ __forceinline__ void mma_tile(
    const uint32_t* __restrict__ Ab, const uint32_t* __restrict__ Bb,
    float (&acc)[4][4][4], int wm0, int wn0, int g, int tg)
{
    #pragma unroll
    for (int kk = 0; kk < 2; kk++) {
        int kb = kk*8;
        uint32_t a[4][4], b[4][2];
        #pragma unroll
        for (int mi = 0; mi < 4; mi++) {
            const uint32_t* base = Ab + (wm0 + mi*16 + g)*AST + kb + tg;
            a[mi][0] = base[0];
            a[mi][1] = base[8*AST];
            a[mi][2] = base[4];
            a[mi][3] = base[8*AST + 4];
        }
        #pragma unroll
        for (int ni = 0; ni < 4; ni++) {
            const uint32_t* base = Bb + (wn0 + ni*8 + g)*RSTRIDE + kb + tg;
            b[ni][0] = base[0];
            b[ni][1] = base[4];
        }
        #pragma unroll
        for (int mi = 0; mi < 4; mi++)
            #pragma unroll
            for (int ni = 0; ni < 4; ni++)
                asm volatile(
                    "mma.sync.aligned.m16n8k16.row.col.f32.f16.f16.f32 "
                    "{%0,%1,%2,%3}, {%4,%5,%6,%7}, {%8,%9}, {%0,%1,%2,%3};"
                    : "+f"(acc[mi][ni][0]), "+f"(acc[mi][ni][1]),
                      "+f"(acc[mi][ni][2]), "+f"(acc[mi][ni][3])
                    : "r"(a[mi][0]), "r"(a[mi][1]), "r"(a[mi][2]), "r"(a[mi][3]),
                      "r"(b[ni][0]), "r"(b[ni][1]));
    }
}

__device__ __forceinline__ void gemm_ca(
    const __half* __restrict__ Ah, const __half* __restrict__ Wh,
    int m0, int n0, float (&acc)[4][4][4],
    uint32_t* __restrict__ dsm, int tid)
{
    const int lane = tid & 31, wid = tid >> 5;
    const int g = lane >> 2, tg = lane & 3;
    const int wm0 = (wid & 1) * 64, wn0 = (wid >> 1) * 32;
    const int row = tid >> 1;
    const int hc  = (tid & 1) * 16;
    const int wc  = (tid & 1) * 8;
    const uint32_t sbase = (uint32_t)__cvta_generic_to_shared(dsm);

    const __half* arow = Ah + (size_t)(m0+row)*256 + hc;
    const __half* brow = Wh + (size_t)(n0+row)*256 + hc;
    const uint32_t adst0 = sbase + (row*RSTRIDE + wc)*4;

    __syncthreads();   // protect smem vs prior use
    #pragma unroll
    for (int p = 0; p < 2; p++) {   // prefetch stages 0,1
        uint32_t as = adst0 + p*STAGE_WORDS*4;
        cp16(as,                      arow + p*32);
        cp16(as + 16,                 arow + p*32 + 8);
        cp16(as + TILE_WORDS*4,       brow + p*32);
        cp16(as + TILE_WORDS*4 + 16,  brow + p*32 + 8);
        cp_commit();
    }
    #pragma unroll
    for (int it = 0; it < 8; it++) {
        if (it < 7) cp_wait<1>(); else cp_wait<0>();
        __syncthreads();    // tile `it` visible to all; compute(it-1) done everywhere
        if (it + 2 < 8) {
            int s = (it+2) % 3;
            uint32_t as = adst0 + s*STAGE_WORDS*4;
            cp16(as,                      arow + (it+2)*32);
            cp16(as + 16,                 arow + (it+2)*32 + 8);
            cp16(as + TILE_WORDS*4,       brow + (it+2)*32);
            cp16(as + TILE_WORDS*4 + 16,  brow + (it+2)*32 + 8);
            cp_commit();
        }
        const uint32_t* Ab = dsm + (it%3)*STAGE_WORDS;
        const uint32_t* Bb = Ab + TILE_WORDS;
        mma_tile<RSTRIDE>(Ab, Bb, acc, wm0, wn0, g, tg);
    }
}

// ---------------- params ---------------------------------------------------------
__global__ void k_params(const float* __restrict__ pl) {
    int i = blockIdx.x*blockDim.x + threadIdx.x;
    if (i < E*D) {
        float nu  = expf(pl[i]);
        float th  = expf(pl[E*D + i]);
        float gm  = expf(pl[2*E*D + i]);
        float mag = expf(-nu);
        g_fr[i]  = mag * cosf(th);
        g_fi[i]  = mag * sinf(th);
        g_gam[i] = gm;
    }
}

// ---------------- weight prep: transpose (+negate imag-mid) -> fp16 [u][n][k] ----
__global__ void k_wprep(const float* __restrict__ ipw, const float* __restrict__ mw,
                        const float* __restrict__ fw1, const float* __restrict__ fw2)
{
    int i = blockIdx.x*256 + threadIdx.x;       // over 28*65536
    int u = i >> 16; int nk = i & 65535;
    int n = nk >> 8, k = nk & 255;
    const float* src; float sgn = 1.f;
    if (u < 12)      src = ipw + (size_t)u*65536;
    else if (u < 16) src = mw  + (size_t)(u-12)*65536;
    else if (u < 20) { src = mw + (size_t)(u-16+4)*65536; sgn = -1.f; }
    else if (u < 24) src = fw1 + (size_t)(u-20)*65536;
    else             src = fw2 + (size_t)(u-24)*65536;
    g_wt[i] = __float2half(sgn * src[k*256 + n]);
}

// ---------------- x -> fp16 ------------------------------------------------------
__global__ void k_xh(const float* __restrict__ x) {
    int i = blockIdx.x*256 + threadIdx.x;       // over M*DIN/4
    float4 v = *(const float4*)(x + (size_t)i*4);
    *(uint2*)(g_xh + (size_t)i*4) = make_uint2(h2pack(v.x, v.y), h2pack(v.z, v.w));
}

// ---------------- in_proj: A-resident, 6 passes (3 units x 2 n-halves) ----------
__global__ void __launch_bounds__(256, 2) k_inproj(const float* __restrict__ bias)
{
    extern __shared__ uint32_t dsm[];
    uint32_t* Asm = dsm;                 // resident A: 128 rows x 128 words (stride 132)
    uint32_t* Bsm = dsm + A_WORDS;       // 3 B stages
    int m0 = blockIdx.x*128; int e = blockIdx.y;
    int tid = threadIdx.x;
    const int lane = tid & 31, wid = tid >> 5;
    const int g = lane >> 2, tg = lane & 3;
    const int wm0 = (wid & 1) * 64, wn0 = (wid >> 1) * 32;
    const int row = tid >> 1;
    const int hc  = (tid & 1) * 16;      // B: half-col base within 32-half chunk
    const int wc  = (tid & 1) * 8;       // B: word-col base
    const uint32_t sbase = (uint32_t)__cvta_generic_to_shared(dsm);
    const uint32_t bbase = sbase + A_WORDS*4;

    // stage full A (row m0+row, halves (tid&1)*128 .. +127)
    {
        const __half* arow = g_xh + (size_t)(m0+row)*256 + (tid&1)*128;
        uint32_t adst = sbase + (row*A_RSTRIDE + (tid&1)*64)*4;
        #pragma unroll
        for (int j = 0; j < 16; j++) cp16(adst + j*16, arow + j*8);
        cp_commit();
    }

    const uint32_t bdst0 = bbase + (row*RSTRIDE + wc)*4;
    #pragma unroll 1
    for (int pass = 0; pass < 6; pass++) {
        int ku = pass >> 1, n0 = (pass & 1) * 128;
        int ke = ku*4 + e;
        const __half* brow = g_wt + (size_t)ke*65536 + (size_t)(n0+row)*256 + hc;
        __syncthreads();   // previous pass compute done before B stages reused
        #pragma unroll
        for (int p = 0; p < 2; p++) {
            uint32_t bs = bdst0 + p*TILE_WORDS*4;
            cp16(bs,      brow + p*32);
            cp16(bs + 16, brow + p*32 + 8);
            cp_commit();
        }
        float acc[4][4][4] = {};
        #pragma unroll
        for (int it = 0; it < 8; it++) {
            if (it < 7) cp_wait<1>(); else cp_wait<0>();
            __syncthreads();
            if (it + 2 < 8) {
                int s = (it+2) % 3;
                uint32_t bs = bdst0 + s*TILE_WORDS*4;
                cp16(bs,      brow + (it+2)*32);
                cp16(bs + 16, brow + (it+2)*32 + 8);
                cp_commit();
            }
            const uint32_t* Ab = Asm + it*16;            // A slice: k-cols it*16 words
            const uint32_t* Bb = Bsm + (it%3)*TILE_WORDS;
            mma_tile<A_RSTRIDE>(Ab, Bb, acc, wm0, wn0, g, tg);
        }
        // epilogue
        __half* dh = (ku == 0) ? g_irh : (ku == 1) ? g_iih : g_oh;
        #pragma unroll
        for (int mi = 0; mi < 4; mi++) {
            int r0 = m0 + wm0 + mi*16 + g;
            #pragma unroll
            for (int ni = 0; ni < 4; ni++) {
                int c = n0 + wn0 + ni*8 + 2*tg;
                float b0 = bias[ke*D + c], b1 = bias[ke*D + c + 1];
                float s0 = 1.f, s1 = 1.f;
                if (ku < 2) { s0 = g_gam[e*D + c]; s1 = g_gam[e*D + c + 1]; }
                size_t i0 = ((size_t)e*M + r0    )*D + c;
                size_t i1 = ((size_t)e*M + r0 + 8)*D + c;
                *(uint32_t*)&dh[i0] = h2pack((acc[mi][ni][0] + b0)*s0, (acc[mi][ni][1] + b1)*s1);
                *(uint32_t*)&dh[i1] = h2pack((acc[mi][ni][2] + b0)*s0, (acc[mi][ni][3] + b1)*s1);
            }
        }
    }
}

// ---------------- chunked LRU scan, fp16 storage / fp32 math ---------------------
__global__ void k_scan1() {
    int j = blockIdx.x*blockDim.x + threadIdx.x;
    int d4 = j & 63; int c = (j >> 6) & (CCH-1); int eb = j >> 11;
    int e = eb / NB; int d = d4*4;
    float4 fr = *(const float4*)(g_fr + e*D + d);
    float4 fi = *(const float4*)(g_fi + e*D + d);
    float4 hr = make_float4(0.f,0.f,0.f,0.f), hi = hr;
    size_t idx = ((size_t)eb*T + (size_t)c*CLEN)*D + d;
    #pragma unroll 4
    for (int t = 0; t < CLEN; t++, idx += D) {
        uint2 urp = *(const uint2*)(g_irh + idx);
        uint2 uip = *(const uint2*)(g_iih + idx);
        float2 ur0 = h2f(urp.x), ur1 = h2f(urp.y);
        float2 ui0 = h2f(uip.x), ui1 = h2f(uip.y);
        float4 nr, ni;
        nr.x = fmaf(fr.x, hr.x, fmaf(-fi.x, hi.x, ur0.x));
        ni.x = fmaf(fr.x, hi.x, fmaf( fi.x, hr.x, ui0.x));
        nr.y = fmaf(fr.y, hr.y, fmaf(-fi.y, hi.y, ur0.y));
        ni.y = fmaf(fr.y, hi.y, fmaf( fi.y, hr.y, ui0.y));
        nr.z = fmaf(fr.z, hr.z, fmaf(-fi.z, hi.z, ur1.x));
        ni.z = fmaf(fr.z, hi.z, fmaf( fi.z, hr.z, ui1.x));
        nr.w = fmaf(fr.w, hr.w, fmaf(-fi.w, hi.w, ur1.y));
        ni.w = fmaf(fr.w, hi.w, fmaf( fi.w, hr.w, ui1.y));
        hr = nr; hi = ni;
        *(uint2*)(g_irh + idx) = make_uint2(h2pack(hr.x, hr.y), h2pack(hr.z, hr.w));
        *(uint2*)(g_iih + idx) = make_uint2(h2pack(hi.x, hi.y), h2pack(hi.z, hi.w));
    }
    int fo = (eb*CCH + c)*D + d;
    *(float4*)(g_finr + fo) = hr;
    *(float4*)(g_fini + fo) = hi;
}

__global__ void k_carry(float* __restrict__ hid) {
    int i = blockIdx.x*blockDim.x + threadIdx.x;
    int d = i % D; int eb = i / D; int e = eb / NB, b = eb % NB;
    float fr = g_fr[e*D+d], fi = g_fi[e*D+d];
    float pr = fr, pi = fi;                     // f^CLEN via 5 squarings (CLEN=32)
    #pragma unroll
    for (int s = 0; s < 5; s++) { float nr = pr*pr - pi*pi, ni2 = 2.f*pr*pi; pr = nr; pi = ni2; }
    float sr = 0.f, si = 0.f;
    #pragma unroll
    for (int c = 0; c < CCH; c++) {
        int j = (eb*CCH + c)*D + d;
        float tr = pr*sr - pi*si + g_finr[j];
        float ti = pr*si + pi*sr + g_fini[j];
        sr = tr; si = ti;
        g_Sr[j] = sr; g_Si[j] = si;
    }
    hid[b*(2*E*D) + e*D + d]         = sr;
    hid[b*(2*E*D) + E*D + e*D + d]   = si;
}

__global__ void k_scan2() {
    int j = blockIdx.x*blockDim.x + threadIdx.x;
    int d4 = j & 63; int c = (j >> 6) & (CCH-1); int eb = j >> 11;
    if (c == 0) return;
    int e = eb / NB; int d = d4*4;
    float4 fr = *(const float4*)(g_fr + e*D + d);
    float4 fi = *(const float4*)(g_fi + e*D + d);
    int so = (eb*CCH + (c-1))*D + d;
    float4 wr = *(const float4*)(g_Sr + so);
    float4 wi = *(const float4*)(g_Si + so);
    size_t idx = ((size_t)eb*T + (size_t)c*CLEN)*D + d;
    #pragma unroll 4
    for (int t = 0; t < CLEN; t++, idx += D) {
        float4 nr, ni;
        nr.x = wr.x*fr.x - wi.x*fi.x;  ni.x = wr.x*fi.x + wi.x*fr.x;
        nr.y = wr.y*fr.y - wi.y*fi.y;  ni.y = wr.y*fi.y + wi.y*fr.y;
        nr.z = wr.z*fr.z - wi.z*fi.z;  ni.z = wr.z*fi.z + wi.z*fr.z;
        nr.w = wr.w*fr.w - wi.w*fi.w;  ni.w = wr.w*fi.w + wi.w*fr.w;
        wr = nr; wi = ni;
        uint2 vrp = *(const uint2*)(g_irh + idx);
        uint2 vip = *(const uint2*)(g_iih + idx);
        float2 vr0 = h2f(vrp.x), vr1 = h2f(vrp.y);
        float2 vi0 = h2f(vip.x), vi1 = h2f(vip.y);
        *(uint2*)(g_irh + idx) = make_uint2(h2pack(vr0.x + wr.x, vr0.y + wr.y),
                                            h2pack(vr1.x + wr.z, vr1.y + wr.w));
        *(uint2*)(g_iih + idx) = make_uint2(h2pack(vi0.x + wi.x, vi0.y + wi.y),
                                            h2pack(vi1.x + wi.z, vi1.y + wi.w));
    }
}

// ---------------- mid: out = out_r@W0 + out_i@(-W1) + (b0-b1) + o ---------------
__global__ void __launch_bounds__(256, 2) k_mid(const float* __restrict__ mb)
{
    extern __shared__ uint32_t dsm[];
    int m0 = blockIdx.x*128, n0 = blockIdx.y*128, e = blockIdx.z;
    float acc[4][4][4] = {};
    gemm_ca(g_irh + (size_t)e*M*D, g_wt + (size_t)(12+e)*65536, m0, n0, acc, dsm, threadIdx.x);
    gemm_ca(g_iih + (size_t)e*M*D, g_wt + (size_t)(16+e)*65536, m0, n0, acc, dsm, threadIdx.x);
    int lane = threadIdx.x & 31, wid = threadIdx.x >> 5;
    int g = lane >> 2, tg = lane & 3;
    int wm0 = (wid & 1) * 64, wn0 = (wid >> 1) * 32;
    #pragma unroll
    for (int mi = 0; mi < 4; mi++) {
        int r0 = m0 + wm0 + mi*16 + g;
        #pragma unroll
        for (int ni = 0; ni < 4; ni++) {
            int c = n0 + wn0 + ni*8 + 2*tg;
            float b0 = mb[e*D+c]   - mb[(E+e)*D+c];
            float b1 = mb[e*D+c+1] - mb[(E+e)*D+c+1];
            size_t i0 = ((size_t)e*M + r0    )*D + c;
            size_t i1 = ((size_t)e*M + r0 + 8)*D + c;
            float2 o0 = h2f(*(const uint32_t*)&g_oh[i0]);
            float2 o1 = h2f(*(const uint32_t*)&g_oh[i1]);
            *(uint32_t*)&g_outh[i0] = h2pack(acc[mi][ni][0] + b0 + o0.x, acc[mi][ni][1] + b1 + o0.y);
            *(uint32_t*)&g_outh[i1] = h2pack(acc[mi][ni][2] + b0 + o1.x, acc[mi][ni][3] + b1 + o1.y);
        }
    }
}

// ---------------- ff1: h1 = gelu(out@W1 + b1)  (h1 -> g_irh, fp16) ---------------
__device__ __forceinline__ float gelu_f(float v) {
    return 0.5f * v * (1.0f + erff(v * 0.70710678118654752f));
}

__global__ void __launch_bounds__(256, 2) k_ff1(const float* __restrict__ b1)
{
    extern __shared__ uint32_t dsm[];
    int m0 = blockIdx.x*128, n0 = blockIdx.y*128, e = blockIdx.z;
    float acc[4][4][4] = {};
    gemm_ca(g_outh + (size_t)e*M*D, g_wt + (size_t)(20+e)*65536, m0, n0, acc, dsm, threadIdx.x);
    int lane = threadIdx.x & 31, wid = threadIdx.x >> 5;
    int g = lane >> 2, tg = lane & 3;
    int wm0 = (wid & 1) * 64, wn0 = (wid >> 1) * 32;
    #pragma unroll
    for (int mi = 0; mi < 4; mi++) {
        int r0 = m0 + wm0 + mi*16 + g;
        #pragma unroll
        for (int ni = 0; ni < 4; ni++) {
            int c = n0 + wn0 + ni*8 + 2*tg;
            float b0 = b1[e*D+c], bb1 = b1[e*D+c+1];
            size_t i0 = ((size_t)e*M + r0    )*D + c;
            size_t i1 = ((size_t)e*M + r0 + 8)*D + c;
            *(uint32_t*)&g_irh[i0] = h2pack(gelu_f(acc[mi][ni][0] + b0), gelu_f(acc[mi][ni][1] + bb1));
            *(uint32_t*)&g_irh[i1] = h2pack(gelu_f(acc[mi][ni][2] + b0), gelu_f(acc[mi][ni][3] + bb1));
        }
    }
}

// ---------------- ff2: h2 = h1@W2 + b2 + out   (h2 -> g_h2, fp32) ----------------
__global__ void __launch_bounds__(256, 2) k_ff2(const float* __restrict__ b2)
{
    extern __shared__ uint32_t dsm[];
    int m0 = blockIdx.x*128, n0 = blockIdx.y*128, e = blockIdx.z;
    float acc[4][4][4] = {};
    gemm_ca(g_irh + (size_t)e*M*D, g_wt + (size_t)(24+e)*65536, m0, n0, acc, dsm, threadIdx.x);
    int lane = threadIdx.x & 31, wid = threadIdx.x >> 5;
    int g = lane >> 2, tg = lane & 3;
    int wm0 = (wid & 1) * 64, wn0 = (wid >> 1) * 32;
    #pragma unroll
    for (int mi = 0; mi < 4; mi++) {
        int r0 = m0 + wm0 + mi*16 + g;
        #pragma unroll
        for (int ni = 0; ni < 4; ni++) {
            int c = n0 + wn0 + ni*8 + 2*tg;
            float b0 = b2[e*D+c], b1v = b2[e*D+c+1];
            size_t i0 = ((size_t)e*M + r0    )*D + c;
            size_t i1 = ((size_t)e*M + r0 + 8)*D + c;
            float2 o0 = h2f(*(const uint32_t*)&g_outh[i0]);
            float2 o1 = h2f(*(const uint32_t*)&g_outh[i1]);
            *(float2*)&g_h2[i0] = make_float2(acc[mi][ni][0] + b0 + o0.x, acc[mi][ni][1] + b1v + o0.y);
            *(float2*)&g_h2[i1] = make_float2(acc[mi][ni][2] + b0 + o1.x, acc[mi][ni][3] + b1v + o1.y);
        }
    }
}

// ---------------- LayerNorm over (E,D) per (b,t) ---------------------------------
__global__ void k_ln(const float* __restrict__ lnw, const float* __restrict__ lnb,
                     float* __restrict__ out)
{
    int bt = blockIdx.x;
    int d  = threadIdx.x;
    float v[E]; float s = 0.f, s2 = 0.f;
    #pragma unroll
    for (int e = 0; e < E; e++) {
        float x = g_h2[((size_t)e*M + bt)*D + d];
        v[e] = x; s += x; s2 += x*x;
    }
    __shared__ float red[2][8];
    #pragma unroll
    for (int o = 16; o > 0; o >>= 1) {
        s  += __shfl_down_sync(0xffffffffu, s,  o);
        s2 += __shfl_down_sync(0xffffffffu, s2, o);
    }
    int lane = d & 31, w = d >> 5;
    if (lane == 0) { red[0][w] = s; red[1][w] = s2; }
    __syncthreads();
    if (w == 0) {
        s  = (lane < 8) ? red[0][lane] : 0.f;
        s2 = (lane < 8) ? red[1][lane] : 0.f;
        #pragma unroll
        for (int o = 4; o > 0; o >>= 1) {
            s  += __shfl_down_sync(0xffffffffu, s,  o);
            s2 += __shfl_down_sync(0xffffffffu, s2, o);
        }
        if (lane == 0) { red[0][0] = s; red[1][0] = s2; }
    }
    __syncthreads();
    float mean = red[0][0] * (1.0f/1024.0f);
    float var  = red[1][0] * (1.0f/1024.0f) - mean*mean;
    float rinv = rsqrtf(var + 1e-5f);
    #pragma unroll
    for (int e = 0; e < E; e++) {
        out[((size_t)e*M + bt)*D + d] =
            (v[e] - mean) * rinv * lnw[e*D + d] + lnb[e*D + d];
    }
}

// ---------------- launch ---------------------------------------------------------
extern "C" void kernel_launch(void* const* d_in, const int* in_sizes, int n_in,
                              void* d_out, int out_size)
{
    (void)in_sizes; (void)n_in; (void)out_size;
    const float* x   = (const float*)d_in[0];
    const float* ipw = (const float*)d_in[1];
    const float* ipb = (const float*)d_in[2];
    const float* pl  = (const float*)d_in[3];
    const float* mw  = (const float*)d_in[4];
    const float* mb  = (const float*)d_in[5];
    const float* fw1 = (const float*)d_in[6];
    const float* fb1 = (const float*)d_in[7];
    const float* fw2 = (const float*)d_in[8];
    const float* fb2 = (const float*)d_in[9];
    const float* lnw = (const float*)d_in[10];
    const float* lnb = (const float*)d_in[11];
    float* out = (float*)d_out;

    cudaFuncSetAttribute(k_inproj, cudaFuncAttributeMaxDynamicSharedMemorySize, SMEM_IP);
    cudaFuncSetAttribute(k_mid,    cudaFuncAttributeMaxDynamicSharedMemorySize, SMEM_G);
    cudaFuncSetAttribute(k_ff1,    cudaFuncAttributeMaxDynamicSharedMemorySize, SMEM_G);
    cudaFuncSetAttribute(k_ff2,    cudaFuncAttributeMaxDynamicSharedMemorySize, SMEM_G);

    k_params<<<4, 256>>>(pl);
    k_wprep<<<28*256, 256>>>(ipw, mw, fw1, fw2);
    k_xh<<<(M*DIN/4)/256, 256>>>(x);
    dim3 gin(M/128, E);
    k_inproj<<<gin, 256, SMEM_IP>>>(ipb);
    k_scan1<<<(LANES*CCH/4)/256, 256>>>();
    k_carry<<<LANES/256, 256>>>(out + EMD);
    k_scan2<<<(LANES*CCH/4)/256, 256>>>();
    dim3 ge(M/128, 2, E);
    k_mid<<<ge, 256, SMEM_G>>>(mb);
    k_ff1<<<ge, 256, SMEM_G>>>(fb1);
    k_ff2<<<ge, 256, SMEM_G>>>(fb2);
    k_ln<<<M, 256>>>(lnw, lnb, out);
}